// round 11
// baseline (speedup 1.0000x reference)
#include <cuda_runtime.h>
#include <cuda_fp16.h>
#include <cstdint>

#define B_  64
#define T_  1024
#define U_  512
#define NC_ 1536
#define M_  (B_ * T_)          // 65536
#define NREC 128
#define SMEM_FUSED 143360      // 4 h-tiles (66560) + 3 red buffers (76800)
#define SMEM_GEMM 61952

// ---------------- device scratch ----------------
__device__ float    g_xp [(size_t)M_ * NC_];      // layer-0 input projections
__device__ unsigned g_bars[4 * 32];               // 4 group barriers, 128B apart
__device__ __half   g_a16[(size_t)M_ * U_];       // x (fp16) [m][k]
__device__ __half   g_wh0[(size_t)NC_ * U_];      // W0^T hi [n][k]
__device__ __half   g_wl0[(size_t)NC_ * U_];      // W0^T lo
__device__ __half   g_w1f[(size_t)NC_ * U_];      // W1^T fp16 [n][k]
__device__ __half   g_r0 [(size_t)NC_ * U_];      // R0^T fp16 [n][k]
__device__ __half   g_r1 [(size_t)NC_ * U_];      // R1^T fp16
// h exchange: split hi/lo fp16, [par][b][u]
__device__ __half   g_h0hi[2][B_ * U_];
__device__ __half   g_h0lo[2][B_ * U_];
__device__ __half   g_h1hi[2][B_ * U_];
__device__ __half   g_h1lo[2][B_ * U_];

// ---------------- helpers ----------------
static __device__ __forceinline__ float fsig(float x) {
    return __fdividef(1.0f, 1.0f + __expf(-x));
}
static __device__ __forceinline__ float ftanh(float x) {
    return 1.0f - __fdividef(2.0f, __expf(2.0f * x) + 1.0f);
}
static __device__ __forceinline__ uint32_t smem_u32(const void* p) {
    uint32_t a;
    asm("{ .reg .u64 t; cvta.to.shared.u64 t, %1; cvt.u32.u64 %0, t; }"
        : "=r"(a) : "l"(p));
    return a;
}
#define LDSM4(r, addr) \
    asm volatile("ldmatrix.sync.aligned.m8n8.x4.shared.b16 {%0,%1,%2,%3}, [%4];" \
        : "=r"((r)[0]), "=r"((r)[1]), "=r"((r)[2]), "=r"((r)[3]) : "r"(addr))
#define MMA_F16(d, a, b0v, b1v) \
    asm volatile("mma.sync.aligned.m16n8k16.row.col.f32.f16.f16.f32 " \
        "{%0,%1,%2,%3}, {%4,%5,%6,%7}, {%8,%9}, {%0,%1,%2,%3};" \
        : "+f"((d)[0]), "+f"((d)[1]), "+f"((d)[2]), "+f"((d)[3]) \
        : "r"((a)[0]), "r"((a)[1]), "r"((a)[2]), "r"((a)[3]), "r"(b0v), "r"(b1v))
#define CPA16(dst, src) \
    asm volatile("cp.async.cg.shared.global [%0], [%1], 16;" :: "r"(dst), "l"(src))
#define CPA_COMMIT() asm volatile("cp.async.commit_group;")
#define CPA_WAIT0()  asm volatile("cp.async.wait_group 0;" ::: "memory")

static __device__ __forceinline__ void bar_arrive(unsigned* p) {
    asm volatile("red.release.gpu.global.add.u32 [%0], 1;" :: "l"(p) : "memory");
}
static __device__ __forceinline__ void bar_poll(unsigned* p, unsigned target) {
    unsigned cur;
    do {
        asm volatile("ld.acquire.gpu.global.u32 %0, [%1];"
                     : "=r"(cur) : "l"(p) : "memory");
    } while (cur < target);
}

// ---------------- prep: all weight conversions ----------------
__global__ void prep_weights(const float* __restrict__ W0, const float* __restrict__ W1,
                             const float* __restrict__ R0, const float* __restrict__ R1) {
    if (blockIdx.x == 0 && threadIdx.x < 4) g_bars[threadIdx.x * 32] = 0u;
    int i = blockIdx.x * blockDim.x + threadIdx.x;
    if (i < NC_ * U_) {
        int n = i >> 9, k = i & 511;
        float v0 = W0[(size_t)k * NC_ + n];
        __half h0 = __float2half(v0);
        g_wh0[i] = h0;
        g_wl0[i] = __float2half(v0 - __half2float(h0));
        g_w1f[i] = __float2half(W1[(size_t)k * NC_ + n]);
        g_r0[i]  = __float2half(R0[(size_t)k * NC_ + n]);
        g_r1[i]  = __float2half(R1[(size_t)k * NC_ + n]);
    }
}

__global__ void split_x(const float* __restrict__ src) {
    size_t n = (size_t)M_ * U_;
    for (size_t i = (size_t)blockIdx.x * blockDim.x + threadIdx.x; i < n;
         i += (size_t)gridDim.x * blockDim.x)
        g_a16[i] = __float2half(src[i]);
}

// ---------------- layer-0 projection GEMM (unchanged core) ----------------
static __device__ __forceinline__ void gemm_tile(const __half* __restrict__ wh,
                                                 const __half* __restrict__ wl,
                                                 const float* __restrict__ biasv,
                                                 float* __restrict__ Cout,
                                                 int m0, int n0, char* sm, uint32_t sb) {
    float* bias_s = (float*)(sm + 61440);
    const int tid = threadIdx.x, lane = tid & 31, wid = tid >> 5;
    const int wm = wid >> 1, wn = wid & 1;

    if (tid < 128) bias_s[tid] = biasv[n0 + tid];

    const int lrow = tid >> 2, lch = tid & 3;
    auto load_tile = [&](int kt, int stage) {
#pragma unroll
        for (int i = 0; i < 2; i++) {
            int row = lrow + i * 64;
            size_t go = (size_t)row * U_ + kt * 32 + lch * 8;
            uint32_t so = sb + stage * 30720 + row * 80 + lch * 16;
            CPA16(so,         (const char*)g_a16 + 2 * ((size_t)m0 * U_ + go));
            CPA16(so + 10240, (const char*)wh    + 2 * ((size_t)n0 * U_ + go));
            CPA16(so + 20480, (const char*)wl    + 2 * ((size_t)n0 * U_ + go));
        }
        CPA_COMMIT();
    };

    float acc[2][8][4];
#pragma unroll
    for (int f = 0; f < 2; f++)
#pragma unroll
        for (int j = 0; j < 8; j++)
#pragma unroll
            for (int c = 0; c < 4; c++) acc[f][j][c] = 0.f;

    const uint32_t aoff = (uint32_t)((wm * 32 + (lane & 15)) * 80 + ((lane >> 4) * 8) * 2);
    const uint32_t boff = (uint32_t)((wn * 64 + (lane & 7) + ((lane >> 4) & 1) * 8) * 80
                                     + (((lane >> 3) & 1) * 8) * 2);

    load_tile(0, 0);
    CPA_WAIT0();
    __syncthreads();

    int buf = 0;
#pragma unroll 1
    for (int kt = 0; kt < 16; kt++) {
        if (kt < 15) load_tile(kt + 1, buf ^ 1);
        const uint32_t sbase = sb + buf * 30720;
#pragma unroll
        for (int ks = 0; ks < 2; ks++) {
            const uint32_t kb = (uint32_t)(ks * 32);
            uint32_t a[2][4], bh[4][4], bl[4][4];
            LDSM4(a[0], sbase + aoff + kb);
            LDSM4(a[1], sbase + aoff + kb + 16 * 80);
#pragma unroll
            for (int p = 0; p < 4; p++) {
                LDSM4(bh[p], sbase + 10240 + boff + kb + p * 16 * 80);
                LDSM4(bl[p], sbase + 20480 + boff + kb + p * 16 * 80);
            }
#pragma unroll
            for (int f = 0; f < 2; f++)
#pragma unroll
                for (int j = 0; j < 8; j++) {
                    uint32_t h0 = bh[j >> 1][(j & 1) * 2], h1 = bh[j >> 1][(j & 1) * 2 + 1];
                    uint32_t l0 = bl[j >> 1][(j & 1) * 2], l1 = bl[j >> 1][(j & 1) * 2 + 1];
                    MMA_F16(acc[f][j], a[f], h0, h1);
                    MMA_F16(acc[f][j], a[f], l0, l1);
                }
        }
        if (kt < 15) {
            CPA_WAIT0();
            __syncthreads();
            buf ^= 1;
        }
    }

#pragma unroll
    for (int f = 0; f < 2; f++) {
        const int r0 = m0 + wm * 32 + f * 16 + (lane >> 2);
#pragma unroll
        for (int j = 0; j < 8; j++) {
            const int cl = wn * 64 + j * 8 + (lane & 3) * 2;
            const int cg = n0 + cl;
            float2 o0 = make_float2(acc[f][j][0] + bias_s[cl], acc[f][j][1] + bias_s[cl + 1]);
            float2 o1 = make_float2(acc[f][j][2] + bias_s[cl], acc[f][j][3] + bias_s[cl + 1]);
            *(float2*)(Cout + (size_t)r0 * NC_ + cg)       = o0;
            *(float2*)(Cout + (size_t)(r0 + 8) * NC_ + cg) = o1;
        }
    }
}

__global__ __launch_bounds__(256) void gemm_mma(const float* __restrict__ bias) {
    extern __shared__ char smg[];
    gemm_tile(g_wh0, g_wl0, bias, g_xp, blockIdx.y * 128, blockIdx.x * 128,
              smg, smem_u32(smg));
}

// ---------------- fused wavefront recurrence: both layers, 1025 supersteps ----------------
// CTA: 16 b x 16 u (48 gate cols per layer). 8 warps k-split 64.
// smem: h0hi@0, h0lo@16640, h1hi@33280, h1lo@49920 (each 16 rows x 1040B);
//       red@66560: 3 sets x [8][16][50] f32 (25600B per set).
__global__ __launch_bounds__(256, 1) void fused_rec(const float* __restrict__ b0v,
                                                    const float* __restrict__ b1v,
                                                    float* __restrict__ out1,
                                                    float* __restrict__ hlast0,
                                                    float* __restrict__ hlast1) {
    extern __shared__ char smb[];
    const uint32_t sb = smem_u32(smb);
    float* red0 = (float*)(smb + 66560);
    float* red1 = (float*)(smb + 66560 + 25600);
    float* red2 = (float*)(smb + 66560 + 51200);

    const int tid = threadIdx.x;
    const int bid = blockIdx.x;
    const int bg = bid >> 5, ug = bid & 31;
    const int b_base = bg * 16, u_base = ug * 16;
    unsigned* mybar = &g_bars[bg * 32];

    const int lane = tid & 31, w = tid >> 5;
    const int kbase = w * 64;
    const int kq = (lane & 3) * 2;

    // ---- preload R0, R1 fragments into registers ----
    uint32_t rb0[6][4][2], rb1[6][4][2];
    uint32_t w1o[6];   // element offsets into g_w1f for this warp's fragment rows
    {
        const int nl = lane >> 2;
#pragma unroll
        for (int nt = 0; nt < 6; nt++) {
            int ncol = nt * 8 + nl;
            int g = ncol >> 4, ul = ncol & 15;
            uint32_t nglob = (uint32_t)(g * 512 + u_base + ul);
            w1o[nt] = nglob * 512u;
            const __half* rp0 = g_r0 + (size_t)nglob * 512;
            const __half* rp1 = g_r1 + (size_t)nglob * 512;
#pragma unroll
            for (int ks = 0; ks < 4; ks++) {
                int k0 = kbase + ks * 16 + kq;
                rb0[nt][ks][0] = *(const uint32_t*)(rp0 + k0);
                rb0[nt][ks][1] = *(const uint32_t*)(rp0 + k0 + 8);
                rb1[nt][ks][0] = *(const uint32_t*)(rp1 + k0);
                rb1[nt][ks][1] = *(const uint32_t*)(rp1 + k0 + 8);
            }
        }
    }

    // owner identity
    const int b_loc = tid >> 4, u_loc = tid & 15;
    const int b_glob = b_base + b_loc, u_glob = u_base + u_loc;
    const float bz0  = b0v[NC_ + u_glob];
    const float brr0 = b0v[NC_ + U_ + u_glob];
    const float bhh0 = b0v[NC_ + 2 * U_ + u_glob];
    const float cz1  = b1v[u_glob] + b1v[NC_ + u_glob];
    const float cr1  = b1v[U_ + u_glob] + b1v[NC_ + U_ + u_glob];
    const float bi1h = b1v[2 * U_ + u_glob];
    const float bh1h = b1v[NC_ + 2 * U_ + u_glob];
    const float* xpp = g_xp + (size_t)b_glob * T_ * NC_;
    float* yrow = out1 + (size_t)b_glob * T_ * U_ + u_glob;
    const size_t hoff = (size_t)b_glob * U_ + u_glob;

    const uint32_t a0off = sb + (uint32_t)((lane & 15) * 1040 + (lane >> 4) * 16 + kbase * 2);
    const uint32_t a1off = a0off + 33280;

    // cp.async chunk mapping: 4 chunks/thread per 16KB tile
    const int c0 = tid * 4;

    float xz = __ldg(xpp + u_glob);
    float xr = __ldg(xpp + U_ + u_glob);
    float xh = __ldg(xpp + 2 * U_ + u_glob);

    __syncthreads();   // rb preloads done (not strictly needed, cheap)

    for (int s = 0; s <= T_; s++) {
        const int par = s & 1;
        // ---- stage h tiles into smem ----
        if (s == 0) {
            for (int i = tid; i < 2080; i += 256)
                ((uint4*)smb)[i] = make_uint4(0u, 0u, 0u, 0u);
        } else {
#pragma unroll
            for (int i = 0; i < 4; i++) {
                int c = c0 + i;
                int row = c >> 6, off16 = (c & 63);
                size_t gsrc = ((size_t)(b_base + row) * U_ + off16 * 8) * 2;
                uint32_t dst = sb + row * 1040 + off16 * 16;
                CPA16(dst,         (const char*)g_h0hi[par] + gsrc);
                CPA16(dst + 16640, (const char*)g_h0lo[par] + gsrc);
            }
            if (s == 1) {
                for (int i = tid; i < 2080; i += 256)
                    ((uint4*)(smb + 33280))[i] = make_uint4(0u, 0u, 0u, 0u);
            } else {
#pragma unroll
                for (int i = 0; i < 4; i++) {
                    int c = c0 + i;
                    int row = c >> 6, off16 = (c & 63);
                    size_t gsrc = ((size_t)(b_base + row) * U_ + off16 * 8) * 2;
                    uint32_t dst = sb + 33280 + row * 1040 + off16 * 16;
                    CPA16(dst,         (const char*)g_h1hi[par] + gsrc);
                    CPA16(dst + 16640, (const char*)g_h1lo[par] + gsrc);
                }
            }
            CPA_COMMIT();
            CPA_WAIT0();
        }
        __syncthreads();

        // ---- mma sets ----
        uint32_t ahi[4][4], alo[4][4];
#pragma unroll
        for (int ks = 0; ks < 4; ks++) {
            LDSM4(ahi[ks], a0off + ks * 32);
            LDSM4(alo[ks], a0off + 16640 + ks * 32);
        }
        const int m = lane >> 2, nn0 = (lane & 3) * 2;

        if (s < T_) {      // set0: h0 @ R0
            float acc[6][4];
#pragma unroll
            for (int nt = 0; nt < 6; nt++)
#pragma unroll
                for (int c = 0; c < 4; c++) acc[nt][c] = 0.f;
#pragma unroll
            for (int ks = 0; ks < 4; ks++)
#pragma unroll
                for (int nt = 0; nt < 6; nt++)
                    MMA_F16(acc[nt], ahi[ks], rb0[nt][ks][0], rb0[nt][ks][1]);
#pragma unroll
            for (int ks = 0; ks < 4; ks++)
#pragma unroll
                for (int nt = 0; nt < 6; nt++)
                    MMA_F16(acc[nt], alo[ks], rb0[nt][ks][0], rb0[nt][ks][1]);
            float* rw = red0 + (size_t)(w * 16) * 50;
#pragma unroll
            for (int nt = 0; nt < 6; nt++) {
                *(float2*)(rw + m * 50 + nt * 8 + nn0)       = make_float2(acc[nt][0], acc[nt][1]);
                *(float2*)(rw + (m + 8) * 50 + nt * 8 + nn0) = make_float2(acc[nt][2], acc[nt][3]);
            }
        }

        if (s >= 1) {      // set1: y0 (=h0) @ W1 ; set2: h1 @ R1
            float acc[6][4];
#pragma unroll
            for (int nt = 0; nt < 6; nt++)
#pragma unroll
                for (int c = 0; c < 4; c++) acc[nt][c] = 0.f;
#pragma unroll
            for (int ks = 0; ks < 4; ks++) {
                const int k0 = kbase + ks * 16 + kq;
#pragma unroll
                for (int nt = 0; nt < 6; nt++) {
                    uint32_t w0 = __ldg((const uint32_t*)(g_w1f + w1o[nt] + k0));
                    uint32_t w1v = __ldg((const uint32_t*)(g_w1f + w1o[nt] + k0 + 8));
                    MMA_F16(acc[nt], ahi[ks], w0, w1v);
                    MMA_F16(acc[nt], alo[ks], w0, w1v);
                }
            }
            float* rw = red1 + (size_t)(w * 16) * 50;
#pragma unroll
            for (int nt = 0; nt < 6; nt++) {
                *(float2*)(rw + m * 50 + nt * 8 + nn0)       = make_float2(acc[nt][0], acc[nt][1]);
                *(float2*)(rw + (m + 8) * 50 + nt * 8 + nn0) = make_float2(acc[nt][2], acc[nt][3]);
            }

            // set2
#pragma unroll
            for (int ks = 0; ks < 4; ks++) {
                LDSM4(ahi[ks], a1off + ks * 32);
                LDSM4(alo[ks], a1off + 16640 + ks * 32);
            }
#pragma unroll
            for (int nt = 0; nt < 6; nt++)
#pragma unroll
                for (int c = 0; c < 4; c++) acc[nt][c] = 0.f;
#pragma unroll
            for (int ks = 0; ks < 4; ks++)
#pragma unroll
                for (int nt = 0; nt < 6; nt++)
                    MMA_F16(acc[nt], ahi[ks], rb1[nt][ks][0], rb1[nt][ks][1]);
#pragma unroll
            for (int ks = 0; ks < 4; ks++)
#pragma unroll
                for (int nt = 0; nt < 6; nt++)
                    MMA_F16(acc[nt], alo[ks], rb1[nt][ks][0], rb1[nt][ks][1]);
            rw = red2 + (size_t)(w * 16) * 50;
#pragma unroll
            for (int nt = 0; nt < 6; nt++) {
                *(float2*)(rw + m * 50 + nt * 8 + nn0)       = make_float2(acc[nt][0], acc[nt][1]);
                *(float2*)(rw + (m + 8) * 50 + nt * 8 + nn0) = make_float2(acc[nt][2], acc[nt][3]);
            }
        }
        __syncthreads();

        // ---- owner phase ----
        if (s < T_) {      // L0 gates -> h0_s
            float s0 = 0.f, s1 = 0.f, s2 = 0.f;
#pragma unroll
            for (int ww = 0; ww < 8; ww++) {
                const float* rr = red0 + (size_t)(ww * 16 + b_loc) * 50;
                s0 += rr[u_loc];
                s1 += rr[16 + u_loc];
                s2 += rr[32 + u_loc];
            }
            float hold = __half2float(((__half*)smb)[b_loc * 520 + u_glob]) +
                         __half2float(((__half*)(smb + 16640))[b_loc * 520 + u_glob]);
            float z  = fsig(xz + s0 + bz0);
            float r  = fsig(xr + s1 + brr0);
            float hh = ftanh(xh + r * (s2 + bhh0));
            float hn = z * hold + (1.0f - z) * hh;
            __half hi = __float2half(hn);
            g_h0hi[1 - par][hoff] = hi;
            g_h0lo[1 - par][hoff] = __float2half(hn - __half2float(hi));
            if (s == T_ - 1) hlast0[hoff] = hn;
        }
        if (s >= 1) {      // L1 gates -> h1_{s-1}, y1 row s-1
            float p0 = 0.f, p1 = 0.f, p2 = 0.f, q0 = 0.f, q1 = 0.f, q2 = 0.f;
#pragma unroll
            for (int ww = 0; ww < 8; ww++) {
                const float* ra = red1 + (size_t)(ww * 16 + b_loc) * 50;
                const float* rb = red2 + (size_t)(ww * 16 + b_loc) * 50;
                p0 += ra[u_loc];
                p1 += ra[16 + u_loc];
                p2 += ra[32 + u_loc];
                q0 += rb[u_loc];
                q1 += rb[16 + u_loc];
                q2 += rb[32 + u_loc];
            }
            float hold = __half2float(((__half*)(smb + 33280))[b_loc * 520 + u_glob]) +
                         __half2float(((__half*)(smb + 49920))[b_loc * 520 + u_glob]);
            float z  = fsig(p0 + q0 + cz1);
            float r  = fsig(p1 + q1 + cr1);
            float hh = ftanh(p2 + bi1h + r * (q2 + bh1h));
            float hn = z * hold + (1.0f - z) * hh;
            yrow[(size_t)(s - 1) * U_] = hn;
            if (s <= T_ - 1) {
                __half hi = __float2half(hn);
                g_h1hi[1 - par][hoff] = hi;
                g_h1lo[1 - par][hoff] = __float2half(hn - __half2float(hi));
            }
            if (s == T_) hlast1[hoff] = hn;
        }

        // ---- barrier + x prefetch ----
        if (s < T_) {
            if (s + 1 < T_) {
                xz = __ldg(xpp + (size_t)(s + 1) * NC_ + u_glob);
                xr = __ldg(xpp + (size_t)(s + 1) * NC_ + U_ + u_glob);
                xh = __ldg(xpp + (size_t)(s + 1) * NC_ + 2 * U_ + u_glob);
            }
            __syncthreads();
            if (tid == 0) {
                bar_arrive(mybar);
                bar_poll(mybar, 32u * (unsigned)(s + 1));
            }
            __syncthreads();
        }
    }
}

// ---------------- launcher ----------------
extern "C" void kernel_launch(void* const* d_in, const int* in_sizes, int n_in,
                              void* d_out, int out_size) {
    const float* x  = (const float*)d_in[0];
    const float* W0 = (const float*)d_in[1];
    const float* R0 = (const float*)d_in[2];
    const float* b0 = (const float*)d_in[3];
    const float* W1 = (const float*)d_in[4];
    const float* R1 = (const float*)d_in[5];
    const float* b1 = (const float*)d_in[6];

    float* out  = (float*)d_out;
    float* out1 = out;                               // [64,1024,512]
    float* h0   = out + (size_t)B_ * T_ * U_;        // [64,512]
    float* h1   = h0 + (size_t)B_ * U_;              // [64,512]

    cudaFuncSetAttribute(fused_rec, cudaFuncAttributeMaxDynamicSharedMemorySize,
                         SMEM_FUSED);
    cudaFuncSetAttribute(gemm_mma, cudaFuncAttributeMaxDynamicSharedMemorySize,
                         SMEM_GEMM);

    prep_weights<<<NC_ * U_ / 256, 256>>>(W0, W1, R0, R1);   // 0
    split_x<<<4096, 256>>>(x);                               // 1
    dim3 g0(12, 512);
    gemm_mma<<<g0, 256, SMEM_GEMM>>>(b0);                    // 2
    fused_rec<<<NREC, 256, SMEM_FUSED>>>(b0, b1, out1, h0, h1);  // 3 -> ncu
}

// round 12
// speedup vs baseline: 1.2072x; 1.2072x over previous
#include <cuda_runtime.h>
#include <cuda_fp16.h>
#include <cstdint>

#define B_  64
#define T_  1024
#define U_  512
#define NC_ 1536
#define M_  (B_ * T_)          // 65536
#define NREC 128
#define NCHASE 20
#define CHASE_TILES 1536       // t-chunks 0..1 of gemm1 (768 tiles per chunk)
#define SMEM_REC_BYTES 122880  // forces 1 CTA/SM for the persistent grid
#define SMEM_GEMM 61952        // 2 stages * 30720 + 512 bias

// ---------------- device scratch (~R6/R10 footprint, which passed) ----------------
__device__ float    g_xp [(size_t)M_ * NC_];      // projections (layer 0, then layer 1 in-place)
__device__ __half   g_hx [2][B_ * U_];            // h exchange: single fp16, [par][b][u]
__device__ unsigned g_bars[4 * 32];               // 4 group barriers, 128B apart
__device__ __half   g_a16[(size_t)M_ * U_];       // A (fp16) [m][k] — x, then y0
__device__ __half   g_wh0[(size_t)NC_ * U_];      // W0^T hi [n][k]
__device__ __half   g_wl0[(size_t)NC_ * U_];
__device__ __half   g_wh1[(size_t)NC_ * U_];      // W1^T hi
__device__ __half   g_wl1[(size_t)NC_ * U_];
__device__ __half   g_r0 [(size_t)NC_ * U_];      // R0^T fp16 [n][k]
__device__ __half   g_r1 [(size_t)NC_ * U_];      // R1^T fp16

// ---------------- helpers ----------------
static __device__ __forceinline__ float fsig(float x) {
    return __fdividef(1.0f, 1.0f + __expf(-x));
}
static __device__ __forceinline__ float ftanh(float x) {
    return 1.0f - __fdividef(2.0f, __expf(2.0f * x) + 1.0f);
}
static __device__ __forceinline__ uint32_t smem_u32(const void* p) {
    uint32_t a;
    asm("{ .reg .u64 t; cvta.to.shared.u64 t, %1; cvt.u32.u64 %0, t; }"
        : "=r"(a) : "l"(p));
    return a;
}
#define LDSM4(r, addr) \
    asm volatile("ldmatrix.sync.aligned.m8n8.x4.shared.b16 {%0,%1,%2,%3}, [%4];" \
        : "=r"((r)[0]), "=r"((r)[1]), "=r"((r)[2]), "=r"((r)[3]) : "r"(addr))
#define MMA_F16(d, a, b0v, b1v) \
    asm volatile("mma.sync.aligned.m16n8k16.row.col.f32.f16.f16.f32 " \
        "{%0,%1,%2,%3}, {%4,%5,%6,%7}, {%8,%9}, {%0,%1,%2,%3};" \
        : "+f"((d)[0]), "+f"((d)[1]), "+f"((d)[2]), "+f"((d)[3]) \
        : "r"((a)[0]), "r"((a)[1]), "r"((a)[2]), "r"((a)[3]), "r"(b0v), "r"(b1v))
#define CPA16(dst, src) \
    asm volatile("cp.async.cg.shared.global [%0], [%1], 16;" :: "r"(dst), "l"(src))
#define CPA_COMMIT() asm volatile("cp.async.commit_group;")
#define CPA_WAIT0()  asm volatile("cp.async.wait_group 0;" ::: "memory")

static __device__ __forceinline__ void bar_arrive(unsigned* p) {
    asm volatile("red.release.gpu.global.add.u32 [%0], 1;" :: "l"(p) : "memory");
}
static __device__ __forceinline__ void bar_poll(unsigned* p, unsigned target) {
    unsigned cur;
    do {
        asm volatile("ld.acquire.gpu.global.u32 %0, [%1];"
                     : "=r"(cur) : "l"(p) : "memory");
    } while (cur < target);
}

// ---------------- prep: all weight conversions in ONE kernel ----------------
__global__ void prep_weights(const float* __restrict__ W0, const float* __restrict__ W1,
                             const float* __restrict__ R0, const float* __restrict__ R1) {
    if (blockIdx.x == 0 && threadIdx.x < 4) g_bars[threadIdx.x * 32] = 0u;
    int i = blockIdx.x * blockDim.x + threadIdx.x;
    if (i < NC_ * U_) {
        int n = i >> 9, k = i & 511;
        float v0 = W0[(size_t)k * NC_ + n];
        __half h0 = __float2half(v0);
        g_wh0[i] = h0;
        g_wl0[i] = __float2half(v0 - __half2float(h0));
        float v1 = W1[(size_t)k * NC_ + n];
        __half h1 = __float2half(v1);
        g_wh1[i] = h1;
        g_wl1[i] = __float2half(v1 - __half2float(h1));
        g_r0[i] = __float2half(R0[(size_t)k * NC_ + n]);
        g_r1[i] = __float2half(R1[(size_t)k * NC_ + n]);
    }
}

__global__ void split_x(const float* __restrict__ src) {
    size_t n = (size_t)M_ * U_;
    for (size_t i = (size_t)blockIdx.x * blockDim.x + threadIdx.x; i < n;
         i += (size_t)gridDim.x * blockDim.x)
        g_a16[i] = __float2half(src[i]);
}

// ---------------- one 128x128 GEMM tile (2-pass fp16), force-inlined ----------------
static __device__ __forceinline__ void gemm_tile(const __half* __restrict__ wh,
                                                 const __half* __restrict__ wl,
                                                 const float* __restrict__ biasv,
                                                 float* __restrict__ Cout,
                                                 int m0, int n0, char* sm, uint32_t sb) {
    float* bias_s = (float*)(sm + 61440);
    const int tid = threadIdx.x, lane = tid & 31, wid = tid >> 5;
    const int wm = wid >> 1, wn = wid & 1;

    __syncthreads();
    if (tid < 128) bias_s[tid] = biasv[n0 + tid];

    const int lrow = tid >> 2, lch = tid & 3;
    auto load_tile = [&](int kt, int stage) {
#pragma unroll
        for (int i = 0; i < 2; i++) {
            int row = lrow + i * 64;
            size_t go = (size_t)row * U_ + kt * 32 + lch * 8;
            uint32_t so = sb + stage * 30720 + row * 80 + lch * 16;
            CPA16(so,         (const char*)g_a16 + 2 * ((size_t)m0 * U_ + go));
            CPA16(so + 10240, (const char*)wh    + 2 * ((size_t)n0 * U_ + go));
            CPA16(so + 20480, (const char*)wl    + 2 * ((size_t)n0 * U_ + go));
        }
        CPA_COMMIT();
    };

    float acc[2][8][4];
#pragma unroll
    for (int f = 0; f < 2; f++)
#pragma unroll
        for (int j = 0; j < 8; j++)
#pragma unroll
            for (int c = 0; c < 4; c++) acc[f][j][c] = 0.f;

    const uint32_t aoff = (uint32_t)((wm * 32 + (lane & 15)) * 80 + ((lane >> 4) * 8) * 2);
    const uint32_t boff = (uint32_t)((wn * 64 + (lane & 7) + ((lane >> 4) & 1) * 8) * 80
                                     + (((lane >> 3) & 1) * 8) * 2);

    load_tile(0, 0);
    CPA_WAIT0();
    __syncthreads();

    int buf = 0;
#pragma unroll 1
    for (int kt = 0; kt < 16; kt++) {
        if (kt < 15) load_tile(kt + 1, buf ^ 1);
        const uint32_t sbase = sb + buf * 30720;
#pragma unroll
        for (int ks = 0; ks < 2; ks++) {
            const uint32_t kb = (uint32_t)(ks * 32);
            uint32_t a[2][4], bh[4][4], bl[4][4];
            LDSM4(a[0], sbase + aoff + kb);
            LDSM4(a[1], sbase + aoff + kb + 16 * 80);
#pragma unroll
            for (int p = 0; p < 4; p++) {
                LDSM4(bh[p], sbase + 10240 + boff + kb + p * 16 * 80);
                LDSM4(bl[p], sbase + 20480 + boff + kb + p * 16 * 80);
            }
#pragma unroll
            for (int f = 0; f < 2; f++)
#pragma unroll
                for (int j = 0; j < 8; j++) {
                    uint32_t h0 = bh[j >> 1][(j & 1) * 2], h1 = bh[j >> 1][(j & 1) * 2 + 1];
                    uint32_t l0 = bl[j >> 1][(j & 1) * 2], l1 = bl[j >> 1][(j & 1) * 2 + 1];
                    MMA_F16(acc[f][j], a[f], h0, h1);
                    MMA_F16(acc[f][j], a[f], l0, l1);
                }
        }
        if (kt < 15) {
            CPA_WAIT0();
            __syncthreads();
            buf ^= 1;
        }
    }

#pragma unroll
    for (int f = 0; f < 2; f++) {
        const int r0 = m0 + wm * 32 + f * 16 + (lane >> 2);
#pragma unroll
        for (int j = 0; j < 8; j++) {
            const int cl = wn * 64 + j * 8 + (lane & 3) * 2;
            const int cg = n0 + cl;
            float2 o0 = make_float2(acc[f][j][0] + bias_s[cl], acc[f][j][1] + bias_s[cl + 1]);
            float2 o1 = make_float2(acc[f][j][2] + bias_s[cl], acc[f][j][3] + bias_s[cl + 1]);
            *(float2*)(Cout + (size_t)r0 * NC_ + cg)       = o0;
            *(float2*)(Cout + (size_t)(r0 + 8) * NC_ + cg) = o1;
        }
    }
}

// mode 0: layer-0 full. mode 1: layer-1 t-chunks 2..7 in-place.
__global__ __launch_bounds__(256) void gemm_mma(const float* __restrict__ bias, int mode) {
    extern __shared__ char smg[];
    const uint32_t sb = smem_u32(smg);
    int my, n0 = blockIdx.x * 128;
    const __half *wh, *wl;
    if (mode == 0) { my = blockIdx.y; wh = g_wh0; wl = g_wl0; }
    else {
        int yy = blockIdx.y;
        my = (yy / 6) * 8 + 2 + (yy % 6);
        wh = g_wh1; wl = g_wl1;
    }
    gemm_tile(wh, wl, bias, g_xp, my * 128, n0, smg, sb);
}

// ---------------- persistent GRU recurrence (single-fp16 mma, fp32 resident state) ------
// rec CTA: 16 b x 16 u x 3 gates; 8 warps k-split 64. smem: h16 [16][520] @0; red @16640.
__global__ __launch_bounds__(256, 1) void gru_rec(int layer,
                                                  const float* __restrict__ bvec,
                                                  float* __restrict__ yext, int writeSplit,
                                                  float* __restrict__ hlast,
                                                  unsigned bar_base,
                                                  const float* __restrict__ bias1) {
    extern __shared__ char smb[];
    const int tid = threadIdx.x;
    const int bid = blockIdx.x;

    if (bid >= NREC) {
        // chaser: layer-1 projection tiles, t-chunks 0..1, in-place into g_xp (rows dead).
        const uint32_t sb = smem_u32(smb);
        const int cid = bid - NREC;
        for (int tt = cid; tt < CHASE_TILES; tt += NCHASE) {
            int tc = tt / 768, rem = tt % 768;
            int b = rem / 12, nn = rem % 12;
            unsigned need = 32u * (unsigned)(tc * 128 + 128);
            if (tid == 0) bar_poll(&g_bars[(b >> 4) * 32], need);
            __syncthreads();
            gemm_tile(g_wh1, g_wl1, bias1, g_xp, (b * 8 + tc) * 128, nn * 128, smb, sb);
        }
        return;
    }

    float* red = (float*)(smb + 16640);     // [8][16][50] f32
    const __half* R16 = layer ? g_r1 : g_r0;

    const int bg = bid >> 5, ug = bid & 31;
    const int b_base = bg * 16, u_base = ug * 16;
    unsigned* mybar = &g_bars[bg * 32];

    const int lane = tid & 31, w = tid >> 5;
    const int kbase = w * 64;

    // ---- preload R fragments: [6 n-tiles][4 k-steps][2 regs] ----
    uint32_t rb[6][4][2];
    {
        const int nl = lane >> 2, kq = (lane & 3) * 2;
#pragma unroll
        for (int nt = 0; nt < 6; nt++) {
            int ncol = nt * 8 + nl;
            int g = ncol >> 4, ul = ncol & 15;
            const __half* rp = R16 + ((size_t)(g * 512 + u_base + ul)) * 512;
#pragma unroll
            for (int ks = 0; ks < 4; ks++) {
                int k0 = kbase + ks * 16 + kq;
                rb[nt][ks][0] = *(const uint32_t*)(rp + k0);
                rb[nt][ks][1] = *(const uint32_t*)(rp + k0 + 8);
            }
        }
    }

    const int b_loc = tid >> 4, u_loc = tid & 15;
    const int b_glob = b_base + b_loc, u_glob = u_base + u_loc;
    const float bz  = bvec[NC_ + u_glob];
    const float brr = bvec[NC_ + U_ + u_glob];
    const float bhh = bvec[NC_ + 2 * U_ + u_glob];
    const float* xpp = g_xp + (size_t)b_glob * T_ * NC_;
    const size_t orow = (size_t)b_glob * T_ * U_ + u_glob;
    __half* hxw = &g_hx[0][(size_t)b_glob * U_ + u_glob];   // write slot (par toggles)

    const uint32_t sb0 = smem_u32(smb);
    const uint32_t aoff = sb0 + (uint32_t)((lane & 15) * 1040 + (lane >> 4) * 16 + kbase * 2);

    float xz = __ldg(xpp + u_glob);
    float xr = __ldg(xpp + U_ + u_glob);
    float xh = __ldg(xpp + 2 * U_ + u_glob);

    float h_own = 0.0f;                     // fp32 resident state

    for (int t = 0; t < T_; t++) {
        const int par = t & 1;
        // ---- stage h tile [16 b][512 u] fp16 into smem (stride 1040B) ----
        if (t == 0) {
            for (int i = tid; i < 1040; i += 256)
                ((uint4*)smb)[i] = make_uint4(0u, 0u, 0u, 0u);
        } else {
            const __half* hg = g_hx[par];
#pragma unroll
            for (int i = 0; i < 4; i++) {
                int c = tid * 4 + i;                  // 0..1023
                int row = c >> 6, off16 = c & 63;
                CPA16(sb0 + row * 1040 + off16 * 16,
                      (const char*)(hg + (size_t)(b_base + row) * U_ + off16 * 8));
            }
            CPA_COMMIT();
            CPA_WAIT0();
        }
        __syncthreads();

        // ---- mma mainloop: 4 ldsm + 24 HMMA per warp ----
        float acc[6][4];
#pragma unroll
        for (int nt = 0; nt < 6; nt++)
#pragma unroll
            for (int c = 0; c < 4; c++) acc[nt][c] = 0.f;

        uint32_t ah[4][4];
#pragma unroll
        for (int ks = 0; ks < 4; ks++) LDSM4(ah[ks], aoff + ks * 32);
#pragma unroll
        for (int ks = 0; ks < 4; ks++)
#pragma unroll
            for (int nt = 0; nt < 6; nt++)
                MMA_F16(acc[nt], ah[ks], rb[nt][ks][0], rb[nt][ks][1]);

        // ---- store C fragments to red[w][b][n] ----
        {
            const int m = lane >> 2, n0 = (lane & 3) * 2;
            float* rw = red + (size_t)(w * 16) * 50;
#pragma unroll
            for (int nt = 0; nt < 6; nt++) {
                *(float2*)(rw + m * 50 + nt * 8 + n0)       = make_float2(acc[nt][0], acc[nt][1]);
                *(float2*)(rw + (m + 8) * 50 + nt * 8 + n0) = make_float2(acc[nt][2], acc[nt][3]);
            }
        }
        __syncthreads();

        // ---- owner: reduce 8 warps, gates (hold = fp32 register) ----
        float s0 = 0.f, s1 = 0.f, s2 = 0.f;
#pragma unroll
        for (int ww = 0; ww < 8; ww++) {
            const float* rr = red + (size_t)(ww * 16 + b_loc) * 50;
            s0 += rr[u_loc];
            s1 += rr[16 + u_loc];
            s2 += rr[32 + u_loc];
        }
        float z  = fsig(xz + s0 + bz);
        float r  = fsig(xr + s1 + brr);
        float hh = ftanh(xh + r * (s2 + bhh));
        float hn = z * h_own + (1.0f - z) * hh;
        h_own = hn;

        if (writeSplit) {
            g_a16[orow + (size_t)t * U_] = __float2half(hn);
        } else {
            yext[orow + (size_t)t * U_] = hn;
        }

        if (t == T_ - 1) {
            hlast[b_glob * U_ + u_glob] = hn;
        } else {
            unsigned short hv = __half_as_ushort(__float2half(hn));
            asm volatile("st.global.cg.u16 [%0], %1;"
                         :: "l"(hxw + (size_t)(1 - par) * (B_ * U_)), "h"(hv) : "memory");
            float nxz = __ldg(xpp + (size_t)(t + 1) * NC_ + u_glob);
            float nxr = __ldg(xpp + (size_t)(t + 1) * NC_ + U_ + u_glob);
            float nxh = __ldg(xpp + (size_t)(t + 1) * NC_ + 2 * U_ + u_glob);
            __syncthreads();
            if (tid == 0) {
                bar_arrive(mybar);
                bar_poll(mybar, bar_base + 32u * (unsigned)(t + 1));
            }
            __syncthreads();
            xz = nxz; xr = nxr; xh = nxh;
        }
    }
}

// ---------------- launcher ----------------
extern "C" void kernel_launch(void* const* d_in, const int* in_sizes, int n_in,
                              void* d_out, int out_size) {
    const float* x  = (const float*)d_in[0];
    const float* W0 = (const float*)d_in[1];
    const float* R0 = (const float*)d_in[2];
    const float* b0 = (const float*)d_in[3];
    const float* W1 = (const float*)d_in[4];
    const float* R1 = (const float*)d_in[5];
    const float* b1 = (const float*)d_in[6];

    float* out  = (float*)d_out;
    float* out1 = out;                               // [64,1024,512]
    float* h0   = out + (size_t)B_ * T_ * U_;        // [64,512]
    float* h1   = h0 + (size_t)B_ * U_;              // [64,512]

    cudaFuncSetAttribute(gru_rec, cudaFuncAttributeMaxDynamicSharedMemorySize,
                         SMEM_REC_BYTES);
    cudaFuncSetAttribute(gemm_mma, cudaFuncAttributeMaxDynamicSharedMemorySize,
                         SMEM_GEMM);

    prep_weights<<<NC_ * U_ / 256, 256>>>(W0, W1, R0, R1);   // 0
    split_x<<<4096, 256>>>(x);                               // 1
    dim3 g0(12, 512);
    gemm_mma<<<g0, 256, SMEM_GEMM>>>(b0, 0);                 // 2
    gru_rec<<<NREC + NCHASE, 256, SMEM_REC_BYTES>>>(0, b0, nullptr, 1, h0,
                                                    0u, b1);  // 3 -> ncu
    dim3 g1(12, 384);
    gemm_mma<<<g1, 256, SMEM_GEMM>>>(b1, 1);                 // 4
    gru_rec<<<NREC, 256, SMEM_REC_BYTES>>>(1, b1, out1, 0, h1,
                                           32u * (T_ - 1), nullptr);  // 5
}

// round 13
// speedup vs baseline: 1.3852x; 1.1475x over previous
#include <cuda_runtime.h>
#include <cuda_fp16.h>
#include <cstdint>

#define B_  64
#define T_  1024
#define U_  512
#define NC_ 1536
#define M_  (B_ * T_)          // 65536
#define SMEM_WAVE 121856       // L1 needs 119296; >116224 forces 1 CTA/SM
#define SMEM_GEMM 61952

// ---------------- device scratch ----------------
__device__ float    g_xp [(size_t)M_ * NC_];      // layer-0 input projections
__device__ unsigned g_bars[4 * 32];               // group barriers, 128B apart
__device__ __half   g_a16[(size_t)M_ * U_];       // x (fp16) [m][k]
__device__ __half   g_wh0[(size_t)NC_ * U_];      // W0^T hi [n][k]
__device__ __half   g_wl0[(size_t)NC_ * U_];      // W0^T lo
__device__ __half   g_wh1[(size_t)NC_ * U_];      // W1^T fp16 [n][k]
__device__ __half   g_r0 [(size_t)NC_ * U_];      // R0^T fp16 [n][k]
__device__ __half   g_r1 [(size_t)NC_ * U_];      // R1^T fp16
__device__ __half   g_hx0[2][B_ * U_];            // h0 exchange [par][b][u]
__device__ __half   g_hx1[2][B_ * U_];            // h1 exchange [par][b][u]

// ---------------- helpers ----------------
static __device__ __forceinline__ float fsig(float x) {
    return __fdividef(1.0f, 1.0f + __expf(-x));
}
static __device__ __forceinline__ float ftanh(float x) {
    return 1.0f - __fdividef(2.0f, __expf(2.0f * x) + 1.0f);
}
static __device__ __forceinline__ uint32_t smem_u32(const void* p) {
    uint32_t a;
    asm("{ .reg .u64 t; cvta.to.shared.u64 t, %1; cvt.u32.u64 %0, t; }"
        : "=r"(a) : "l"(p));
    return a;
}
#define LDSM4(r, addr) \
    asm volatile("ldmatrix.sync.aligned.m8n8.x4.shared.b16 {%0,%1,%2,%3}, [%4];" \
        : "=r"((r)[0]), "=r"((r)[1]), "=r"((r)[2]), "=r"((r)[3]) : "r"(addr))
#define MMA_F16(d, a, b0v, b1v) \
    asm volatile("mma.sync.aligned.m16n8k16.row.col.f32.f16.f16.f32 " \
        "{%0,%1,%2,%3}, {%4,%5,%6,%7}, {%8,%9}, {%0,%1,%2,%3};" \
        : "+f"((d)[0]), "+f"((d)[1]), "+f"((d)[2]), "+f"((d)[3]) \
        : "r"((a)[0]), "r"((a)[1]), "r"((a)[2]), "r"((a)[3]), "r"(b0v), "r"(b1v))
#define CPA16(dst, src) \
    asm volatile("cp.async.cg.shared.global [%0], [%1], 16;" :: "r"(dst), "l"(src))
#define CPA_COMMIT() asm volatile("cp.async.commit_group;")
#define CPA_WAIT0()  asm volatile("cp.async.wait_group 0;" ::: "memory")
#define STG_H16(p, v) \
    asm volatile("st.global.cg.u16 [%0], %1;" :: "l"(p), "h"(v) : "memory")

static __device__ __forceinline__ void bar_arrive(unsigned* p) {
    asm volatile("red.release.gpu.global.add.u32 [%0], 1;" :: "l"(p) : "memory");
}
static __device__ __forceinline__ void bar_poll(unsigned* p, unsigned target) {
    unsigned cur;
    do {
        asm volatile("ld.acquire.gpu.global.u32 %0, [%1];"
                     : "=r"(cur) : "l"(p) : "memory");
    } while (cur < target);
}

// ---------------- prep: weight conversions ----------------
__global__ void prep_weights(const float* __restrict__ W0, const float* __restrict__ W1,
                             const float* __restrict__ R0, const float* __restrict__ R1) {
    if (blockIdx.x == 0 && threadIdx.x < 4) g_bars[threadIdx.x * 32] = 0u;
    int i = blockIdx.x * blockDim.x + threadIdx.x;
    if (i < NC_ * U_) {
        int n = i >> 9, k = i & 511;
        float v0 = W0[(size_t)k * NC_ + n];
        __half h0 = __float2half(v0);
        g_wh0[i] = h0;
        g_wl0[i] = __float2half(v0 - __half2float(h0));
        g_wh1[i] = __float2half(W1[(size_t)k * NC_ + n]);
        g_r0[i]  = __float2half(R0[(size_t)k * NC_ + n]);
        g_r1[i]  = __float2half(R1[(size_t)k * NC_ + n]);
    }
}

__global__ void split_x(const float* __restrict__ src) {
    size_t n = (size_t)M_ * U_;
    for (size_t i = (size_t)blockIdx.x * blockDim.x + threadIdx.x; i < n;
         i += (size_t)gridDim.x * blockDim.x)
        g_a16[i] = __float2half(src[i]);
}

// ---------------- layer-0 projection GEMM (proven core) ----------------
static __device__ __forceinline__ void gemm_tile(const __half* __restrict__ wh,
                                                 const __half* __restrict__ wl,
                                                 const float* __restrict__ biasv,
                                                 float* __restrict__ Cout,
                                                 int m0, int n0, char* sm, uint32_t sb) {
    float* bias_s = (float*)(sm + 61440);
    const int tid = threadIdx.x, lane = tid & 31, wid = tid >> 5;
    const int wm = wid >> 1, wn = wid & 1;

    if (tid < 128) bias_s[tid] = biasv[n0 + tid];

    const int lrow = tid >> 2, lch = tid & 3;
    auto load_tile = [&](int kt, int stage) {
#pragma unroll
        for (int i = 0; i < 2; i++) {
            int row = lrow + i * 64;
            size_t go = (size_t)row * U_ + kt * 32 + lch * 8;
            uint32_t so = sb + stage * 30720 + row * 80 + lch * 16;
            CPA16(so,         (const char*)g_a16 + 2 * ((size_t)m0 * U_ + go));
            CPA16(so + 10240, (const char*)wh    + 2 * ((size_t)n0 * U_ + go));
            CPA16(so + 20480, (const char*)wl    + 2 * ((size_t)n0 * U_ + go));
        }
        CPA_COMMIT();
    };

    float acc[2][8][4];
#pragma unroll
    for (int f = 0; f < 2; f++)
#pragma unroll
        for (int j = 0; j < 8; j++)
#pragma unroll
            for (int c = 0; c < 4; c++) acc[f][j][c] = 0.f;

    const uint32_t aoff = (uint32_t)((wm * 32 + (lane & 15)) * 80 + ((lane >> 4) * 8) * 2);
    const uint32_t boff = (uint32_t)((wn * 64 + (lane & 7) + ((lane >> 4) & 1) * 8) * 80
                                     + (((lane >> 3) & 1) * 8) * 2);

    load_tile(0, 0);
    CPA_WAIT0();
    __syncthreads();

    int buf = 0;
#pragma unroll 1
    for (int kt = 0; kt < 16; kt++) {
        if (kt < 15) load_tile(kt + 1, buf ^ 1);
        const uint32_t sbase = sb + buf * 30720;
#pragma unroll
        for (int ks = 0; ks < 2; ks++) {
            const uint32_t kb = (uint32_t)(ks * 32);
            uint32_t a[2][4], bh[4][4], bl[4][4];
            LDSM4(a[0], sbase + aoff + kb);
            LDSM4(a[1], sbase + aoff + kb + 16 * 80);
#pragma unroll
            for (int p = 0; p < 4; p++) {
                LDSM4(bh[p], sbase + 10240 + boff + kb + p * 16 * 80);
                LDSM4(bl[p], sbase + 20480 + boff + kb + p * 16 * 80);
            }
#pragma unroll
            for (int f = 0; f < 2; f++)
#pragma unroll
                for (int j = 0; j < 8; j++) {
                    uint32_t h0 = bh[j >> 1][(j & 1) * 2], h1 = bh[j >> 1][(j & 1) * 2 + 1];
                    uint32_t l0 = bl[j >> 1][(j & 1) * 2], l1 = bl[j >> 1][(j & 1) * 2 + 1];
                    MMA_F16(acc[f][j], a[f], h0, h1);
                    MMA_F16(acc[f][j], a[f], l0, l1);
                }
        }
        if (kt < 15) {
            CPA_WAIT0();
            __syncthreads();
            buf ^= 1;
        }
    }

#pragma unroll
    for (int f = 0; f < 2; f++) {
        const int r0 = m0 + wm * 32 + f * 16 + (lane >> 2);
#pragma unroll
        for (int j = 0; j < 8; j++) {
            const int cl = wn * 64 + j * 8 + (lane & 3) * 2;
            const int cg = n0 + cl;
            float2 o0 = make_float2(acc[f][j][0] + bias_s[cl], acc[f][j][1] + bias_s[cl + 1]);
            float2 o1 = make_float2(acc[f][j][2] + bias_s[cl], acc[f][j][3] + bias_s[cl + 1]);
            *(float2*)(Cout + (size_t)r0 * NC_ + cg)       = o0;
            *(float2*)(Cout + (size_t)(r0 + 8) * NC_ + cg) = o1;
        }
    }
}

__global__ __launch_bounds__(256) void gemm_mma(const float* __restrict__ bias) {
    extern __shared__ char smg[];
    gemm_tile(g_wh0, g_wl0, bias, g_xp, blockIdx.y * 128, blockIdx.x * 128,
              smg, smem_u32(smg));
}

// ---------------- split-SM wavefront recurrence ----------------
// CTAs 0..63: layer 0 (2 bg x 32 CTAs; CTA = 32b x 16u; K=512).
// CTAs 64..127: layer 1 (same geometry; combined K=1024 over [y0|h1]).
// Barrier group = 64 CTAs (L0(bg)+L1(bg)); 1025 supersteps.
__global__ __launch_bounds__(256, 1) void wave_rec(const float* __restrict__ b0v,
                                                   const float* __restrict__ b1v,
                                                   float* __restrict__ out1,
                                                   float* __restrict__ hl0,
                                                   float* __restrict__ hl1) {
    extern __shared__ char smb[];
    const uint32_t sb = smem_u32(smb);
    const int tid = threadIdx.x, lane = tid & 31, w = tid >> 5;
    const int bid = blockIdx.x;
    const bool isL1 = bid >= 64;
    const int lb = isL1 ? bid - 64 : bid;
    const int bg = lb >> 5, ug = lb & 31;
    const int b_base = bg * 32, u_base = ug * 16;
    unsigned* mybar = &g_bars[bg * 32];

    const int nl = lane >> 2, kq = (lane & 3) * 2;
    const int m = lane >> 2, n0r = (lane & 3) * 2;
    // owner identity: 2 outputs per thread
    const int b_loc = tid >> 3;           // 0..31
    const int u0 = (tid & 7) * 2;         // 0..14
    const int b_glob = b_base + b_loc;

    if (!isL1) {
        // ================= LAYER 0 =================
        const int kbase = w * 64;
        uint32_t rb[6][4][2];
#pragma unroll
        for (int nt = 0; nt < 6; nt++) {
            int ncol = nt * 8 + nl;
            int g = ncol >> 4, ul = ncol & 15;
            const __half* rp = g_r0 + ((size_t)(g * 512 + u_base + ul)) * 512;
#pragma unroll
            for (int ks = 0; ks < 4; ks++) {
                int k0 = kbase + ks * 16 + kq;
                rb[nt][ks][0] = *(const uint32_t*)(rp + k0);
                rb[nt][ks][1] = *(const uint32_t*)(rp + k0 + 8);
            }
        }

        float bz[2], brr[2], bhhc[2], xz[2], xr[2], xh[2], hown[2];
        const float* xpp = g_xp + (size_t)b_glob * T_ * NC_;
#pragma unroll
        for (int j = 0; j < 2; j++) {
            int ugl = u_base + u0 + j;
            bz[j]   = b0v[NC_ + ugl];
            brr[j]  = b0v[NC_ + U_ + ugl];
            bhhc[j] = b0v[NC_ + 2 * U_ + ugl];
            xz[j] = __ldg(xpp + ugl);
            xr[j] = __ldg(xpp + U_ + ugl);
            xh[j] = __ldg(xpp + 2 * U_ + ugl);
            hown[j] = 0.0f;
        }
        float* red = (float*)(smb + 33280);
        const uint32_t aoff = sb + (uint32_t)((lane & 15) * 1040 + (lane >> 4) * 16 + kbase * 2);

        for (int s = 0; s < T_; s++) {
            if (s == 0) {
                for (int i = tid; i < 2080; i += 256)
                    ((uint4*)smb)[i] = make_uint4(0u, 0u, 0u, 0u);
            } else {
                const __half* hg = g_hx0[1 - (s & 1)];
#pragma unroll
                for (int i = 0; i < 8; i++) {
                    int c = tid * 8 + i;
                    int row = c >> 6, off = c & 63;
                    CPA16(sb + row * 1040 + off * 16,
                          (const char*)(hg + (size_t)(b_base + row) * U_ + off * 8));
                }
                CPA_COMMIT();
                CPA_WAIT0();
            }
            __syncthreads();

            float acc[2][6][4];
#pragma unroll
            for (int mt = 0; mt < 2; mt++)
#pragma unroll
                for (int nt = 0; nt < 6; nt++)
#pragma unroll
                    for (int c = 0; c < 4; c++) acc[mt][nt][c] = 0.f;
#pragma unroll
            for (int ks = 0; ks < 4; ks++) {
                uint32_t a0[4], a1[4];
                LDSM4(a0, aoff + ks * 32);
                LDSM4(a1, aoff + 16 * 1040 + ks * 32);
#pragma unroll
                for (int nt = 0; nt < 6; nt++) {
                    MMA_F16(acc[0][nt], a0, rb[nt][ks][0], rb[nt][ks][1]);
                    MMA_F16(acc[1][nt], a1, rb[nt][ks][0], rb[nt][ks][1]);
                }
            }
#pragma unroll
            for (int mt = 0; mt < 2; mt++)
#pragma unroll
                for (int nt = 0; nt < 6; nt++) {
                    float* r0p = red + (size_t)(w * 32 + mt * 16 + m) * 50 + nt * 8 + n0r;
                    *(float2*)r0p = make_float2(acc[mt][nt][0], acc[mt][nt][1]);
                    *(float2*)(r0p + 8 * 50) = make_float2(acc[mt][nt][2], acc[mt][nt][3]);
                }
            __syncthreads();

#pragma unroll
            for (int j = 0; j < 2; j++) {
                int u_loc = u0 + j;
                float s0 = 0.f, s1 = 0.f, s2 = 0.f;
#pragma unroll
                for (int ww = 0; ww < 8; ww++) {
                    const float* rr = red + (size_t)(ww * 32 + b_loc) * 50;
                    s0 += rr[u_loc];
                    s1 += rr[16 + u_loc];
                    s2 += rr[32 + u_loc];
                }
                float z  = fsig(xz[j] + s0 + bz[j]);
                float r  = fsig(xr[j] + s1 + brr[j]);
                float hh = ftanh(xh[j] + r * (s2 + bhhc[j]));
                float hn = z * hown[j] + (1.0f - z) * hh;
                hown[j] = hn;
                STG_H16(&g_hx0[s & 1][(size_t)b_glob * U_ + u_base + u_loc],
                        __half_as_ushort(__float2half(hn)));
                if (s == T_ - 1) hl0[(size_t)b_glob * U_ + u_base + u_loc] = hn;
            }
            if (s + 1 < T_) {
#pragma unroll
                for (int j = 0; j < 2; j++) {
                    int ugl = u_base + u0 + j;
                    xz[j] = __ldg(xpp + (size_t)(s + 1) * NC_ + ugl);
                    xr[j] = __ldg(xpp + (size_t)(s + 1) * NC_ + U_ + ugl);
                    xh[j] = __ldg(xpp + (size_t)(s + 1) * NC_ + 2 * U_ + ugl);
                }
            }
            __syncthreads();
            if (tid == 0) {
                bar_arrive(mybar);
                if (s < T_ - 1) bar_poll(mybar, 64u * (unsigned)(s + 1));
            }
            __syncthreads();
        }
    } else {
        // ================= LAYER 1 =================
        const int kbaseA = w * 128;
        const __half* WZ = (w < 4) ? g_wh1 : g_r1;
        const int kW = (w < 4) ? kbaseA : kbaseA - 512;

        uint32_t rzr[4][8][2];
#pragma unroll
        for (int nt = 0; nt < 4; nt++) {
            int ncol = nt * 8 + nl;
            int g = ncol >> 4, ul = ncol & 15;
            const __half* rp = WZ + ((size_t)(g * 512 + u_base + ul)) * 512;
#pragma unroll
            for (int ks = 0; ks < 8; ks++) {
                int k0 = kW + ks * 16 + kq;
                rzr[nt][ks][0] = *(const uint32_t*)(rp + k0);
                rzr[nt][ks][1] = *(const uint32_t*)(rp + k0 + 8);
            }
        }
        uint32_t rhh[2][8][2];
#pragma unroll
        for (int nt = 0; nt < 2; nt++) {
            int ul = nt * 8 + nl;
            const __half* rp = WZ + ((size_t)(1024 + u_base + ul)) * 512;
#pragma unroll
            for (int ks = 0; ks < 8; ks++) {
                int k0 = kW + ks * 16 + kq;
                rhh[nt][ks][0] = *(const uint32_t*)(rp + k0);
                rhh[nt][ks][1] = *(const uint32_t*)(rp + k0 + 8);
            }
        }

        float cz[2], cr[2], bih[2], bhh2[2], hown[2];
#pragma unroll
        for (int j = 0; j < 2; j++) {
            int ugl = u_base + u0 + j;
            cz[j]   = b1v[ugl] + b1v[NC_ + ugl];
            cr[j]   = b1v[U_ + ugl] + b1v[NC_ + U_ + ugl];
            bih[j]  = b1v[2 * U_ + ugl];
            bhh2[j] = b1v[NC_ + 2 * U_ + ugl];
            hown[j] = 0.0f;
        }
        float* red = (float*)(smb + 66048);      // [8][32][52]
        const uint32_t aoff = sb + (uint32_t)((lane & 15) * 2064 + (lane >> 4) * 16 + kbaseA * 2);

        for (int s = 0; s <= T_; s++) {
            if (s >= 1) {
                if (s == 1) {
                    for (int i = tid; i < 2048; i += 256) {
                        int row = i >> 6, off = i & 63;
                        *(uint4*)(smb + row * 2064 + 1024 + off * 16) =
                            make_uint4(0u, 0u, 0u, 0u);
                    }
                }
                const __half* hy = g_hx0[(s - 1) & 1];
#pragma unroll
                for (int i = 0; i < 8; i++) {
                    int c = tid * 8 + i;
                    int row = c >> 6, off = c & 63;
                    CPA16(sb + row * 2064 + off * 16,
                          (const char*)(hy + (size_t)(b_base + row) * U_ + off * 8));
                }
                if (s >= 2) {
                    const __half* hh1 = g_hx1[s & 1];
#pragma unroll
                    for (int i = 0; i < 8; i++) {
                        int c = tid * 8 + i;
                        int row = c >> 6, off = c & 63;
                        CPA16(sb + row * 2064 + 1024 + off * 16,
                              (const char*)(hh1 + (size_t)(b_base + row) * U_ + off * 8));
                    }
                }
                CPA_COMMIT();
                CPA_WAIT0();
            }
            __syncthreads();

            if (s >= 1) {
                float acc[2][6][4];
#pragma unroll
                for (int mt = 0; mt < 2; mt++)
#pragma unroll
                    for (int nt = 0; nt < 6; nt++)
#pragma unroll
                        for (int c = 0; c < 4; c++) acc[mt][nt][c] = 0.f;
#pragma unroll
                for (int ks = 0; ks < 8; ks++) {
                    uint32_t a0[4], a1[4];
                    LDSM4(a0, aoff + ks * 32);
                    LDSM4(a1, aoff + 16 * 2064 + ks * 32);
#pragma unroll
                    for (int nt = 0; nt < 4; nt++) {
                        MMA_F16(acc[0][nt], a0, rzr[nt][ks][0], rzr[nt][ks][1]);
                        MMA_F16(acc[1][nt], a1, rzr[nt][ks][0], rzr[nt][ks][1]);
                    }
#pragma unroll
                    for (int nt = 0; nt < 2; nt++) {
                        MMA_F16(acc[0][4 + nt], a0, rhh[nt][ks][0], rhh[nt][ks][1]);
                        MMA_F16(acc[1][4 + nt], a1, rhh[nt][ks][0], rhh[nt][ks][1]);
                    }
                }
#pragma unroll
                for (int mt = 0; mt < 2; mt++) {
#pragma unroll
                    for (int nt = 0; nt < 4; nt++) {
                        float* r0p = red + (size_t)(w * 32 + mt * 16 + m) * 52 + nt * 8 + n0r;
                        *(float2*)r0p = make_float2(acc[mt][nt][0], acc[mt][nt][1]);
                        *(float2*)(r0p + 8 * 52) = make_float2(acc[mt][nt][2], acc[mt][nt][3]);
                    }
#pragma unroll
                    for (int nt = 0; nt < 2; nt++) {
                        float* r0p = red + (size_t)(w * 32 + mt * 16 + m) * 52 + 32 + nt * 8 + n0r;
                        *(float2*)r0p = make_float2(acc[mt][4 + nt][0], acc[mt][4 + nt][1]);
                        *(float2*)(r0p + 8 * 52) = make_float2(acc[mt][4 + nt][2], acc[mt][4 + nt][3]);
                    }
                }
            }
            __syncthreads();

            if (s >= 1) {
#pragma unroll
                for (int j = 0; j < 2; j++) {
                    int u_loc = u0 + j;
                    float zv = 0.f, rv = 0.f, pv = 0.f, qv = 0.f;
#pragma unroll
                    for (int ww = 0; ww < 8; ww++) {
                        const float* rr = red + (size_t)(ww * 32 + b_loc) * 52;
                        zv += rr[u_loc];
                        rv += rr[16 + u_loc];
                        if (ww < 4) pv += rr[32 + u_loc];
                        else        qv += rr[32 + u_loc];
                    }
                    float z  = fsig(zv + cz[j]);
                    float r  = fsig(rv + cr[j]);
                    float hh = ftanh(pv + bih[j] + r * (qv + bhh2[j]));
                    float hn = z * hown[j] + (1.0f - z) * hh;
                    hown[j] = hn;
                    out1[(size_t)b_glob * T_ * U_ + (size_t)(s - 1) * U_ + u_base + u_loc] = hn;
                    if (s <= T_ - 1)
                        STG_H16(&g_hx1[(s - 1) & 1][(size_t)b_glob * U_ + u_base + u_loc],
                                __half_as_ushort(__float2half(hn)));
                    if (s == T_) hl1[(size_t)b_glob * U_ + u_base + u_loc] = hn;
                }
            }

            if (s <= T_ - 1) {
                __syncthreads();
                if (tid == 0) {
                    bar_arrive(mybar);
                    bar_poll(mybar, 64u * (unsigned)(s + 1));
                }
                __syncthreads();
            }
        }
    }
}

// ---------------- launcher ----------------
extern "C" void kernel_launch(void* const* d_in, const int* in_sizes, int n_in,
                              void* d_out, int out_size) {
    const float* x  = (const float*)d_in[0];
    const float* W0 = (const float*)d_in[1];
    const float* R0 = (const float*)d_in[2];
    const float* b0 = (const float*)d_in[3];
    const float* W1 = (const float*)d_in[4];
    const float* R1 = (const float*)d_in[5];
    const float* b1 = (const float*)d_in[6];

    float* out  = (float*)d_out;
    float* out1 = out;                               // [64,1024,512]
    float* h0   = out + (size_t)B_ * T_ * U_;        // [64,512]
    float* h1   = h0 + (size_t)B_ * U_;              // [64,512]

    cudaFuncSetAttribute(wave_rec, cudaFuncAttributeMaxDynamicSharedMemorySize,
                         SMEM_WAVE);
    cudaFuncSetAttribute(gemm_mma, cudaFuncAttributeMaxDynamicSharedMemorySize,
                         SMEM_GEMM);

    prep_weights<<<NC_ * U_ / 256, 256>>>(W0, W1, R0, R1);   // 0
    split_x<<<4096, 256>>>(x);                               // 1
    dim3 g0(12, 512);
    gemm_mma<<<g0, 256, SMEM_GEMM>>>(b0);                    // 2
    wave_rec<<<128, 256, SMEM_WAVE>>>(b0, b1, out1, h0, h1); // 3 -> ncu
}

// round 14
// speedup vs baseline: 1.4044x; 1.0138x over previous
#include <cuda_runtime.h>
#include <cuda_fp16.h>
#include <cstdint>

#define B_  64
#define T_  1024
#define U_  512
#define NC_ 1536
#define M_  (B_ * T_)          // 65536
#define SMEM_WAVE 121856       // L1 needs 119296; >116224 forces 1 CTA/SM
#define SMEM_GEMM 61952

// ---------------- device scratch ----------------
__device__ float    g_xp [(size_t)M_ * NC_];      // layer-0 input projections
__device__ unsigned g_bars[4 * 32];               // [bg*2+layer] counters, 128B apart
__device__ __half   g_a16[(size_t)M_ * U_];       // x (fp16) [m][k]
__device__ __half   g_wh0[(size_t)NC_ * U_];      // W0^T hi [n][k]
__device__ __half   g_wl0[(size_t)NC_ * U_];      // W0^T lo
__device__ __half   g_wh1[(size_t)NC_ * U_];      // W1^T fp16 [n][k]
__device__ __half   g_r0 [(size_t)NC_ * U_];      // R0^T fp16 [n][k]
__device__ __half   g_r1 [(size_t)NC_ * U_];      // R1^T fp16
__device__ __half   g_hx0[3][B_ * U_];            // h0 exchange, TRIPLE buffered
__device__ __half   g_hx1[2][B_ * U_];            // h1 exchange, double buffered

// ---------------- helpers ----------------
static __device__ __forceinline__ float fsig(float x) {
    return __fdividef(1.0f, 1.0f + __expf(-x));
}
static __device__ __forceinline__ float ftanh(float x) {
    return 1.0f - __fdividef(2.0f, __expf(2.0f * x) + 1.0f);
}
static __device__ __forceinline__ uint32_t smem_u32(const void* p) {
    uint32_t a;
    asm("{ .reg .u64 t; cvta.to.shared.u64 t, %1; cvt.u32.u64 %0, t; }"
        : "=r"(a) : "l"(p));
    return a;
}
#define LDSM4(r, addr) \
    asm volatile("ldmatrix.sync.aligned.m8n8.x4.shared.b16 {%0,%1,%2,%3}, [%4];" \
        : "=r"((r)[0]), "=r"((r)[1]), "=r"((r)[2]), "=r"((r)[3]) : "r"(addr))
#define MMA_F16(d, a, b0v, b1v) \
    asm volatile("mma.sync.aligned.m16n8k16.row.col.f32.f16.f16.f32 " \
        "{%0,%1,%2,%3}, {%4,%5,%6,%7}, {%8,%9}, {%0,%1,%2,%3};" \
        : "+f"((d)[0]), "+f"((d)[1]), "+f"((d)[2]), "+f"((d)[3]) \
        : "r"((a)[0]), "r"((a)[1]), "r"((a)[2]), "r"((a)[3]), "r"(b0v), "r"(b1v))
#define CPA16(dst, src) \
    asm volatile("cp.async.cg.shared.global [%0], [%1], 16;" :: "r"(dst), "l"(src))
#define CPA_COMMIT() asm volatile("cp.async.commit_group;")
#define CPA_WAIT0()  asm volatile("cp.async.wait_group 0;" ::: "memory")
#define STG_H16(p, v) \
    asm volatile("st.global.cg.u16 [%0], %1;" :: "l"(p), "h"(v) : "memory")

static __device__ __forceinline__ void bar_arrive(unsigned* p) {
    asm volatile("red.release.gpu.global.add.u32 [%0], 1;" :: "l"(p) : "memory");
}
static __device__ __forceinline__ void bar_poll(unsigned* p, unsigned target) {
    unsigned cur;
    do {
        asm volatile("ld.acquire.gpu.global.u32 %0, [%1];"
                     : "=r"(cur) : "l"(p) : "memory");
    } while (cur < target);
}

// ---------------- prep: weight conversions ----------------
__global__ void prep_weights(const float* __restrict__ W0, const float* __restrict__ W1,
                             const float* __restrict__ R0, const float* __restrict__ R1) {
    if (blockIdx.x == 0 && threadIdx.x < 4) g_bars[threadIdx.x * 32] = 0u;
    int i = blockIdx.x * blockDim.x + threadIdx.x;
    if (i < NC_ * U_) {
        int n = i >> 9, k = i & 511;
        float v0 = W0[(size_t)k * NC_ + n];
        __half h0 = __float2half(v0);
        g_wh0[i] = h0;
        g_wl0[i] = __float2half(v0 - __half2float(h0));
        g_wh1[i] = __float2half(W1[(size_t)k * NC_ + n]);
        g_r0[i]  = __float2half(R0[(size_t)k * NC_ + n]);
        g_r1[i]  = __float2half(R1[(size_t)k * NC_ + n]);
    }
}

__global__ void split_x(const float* __restrict__ src) {
    size_t n = (size_t)M_ * U_;
    for (size_t i = (size_t)blockIdx.x * blockDim.x + threadIdx.x; i < n;
         i += (size_t)gridDim.x * blockDim.x)
        g_a16[i] = __float2half(src[i]);
}

// ---------------- layer-0 projection GEMM (proven core) ----------------
static __device__ __forceinline__ void gemm_tile(const __half* __restrict__ wh,
                                                 const __half* __restrict__ wl,
                                                 const float* __restrict__ biasv,
                                                 float* __restrict__ Cout,
                                                 int m0, int n0, char* sm, uint32_t sb) {
    float* bias_s = (float*)(sm + 61440);
    const int tid = threadIdx.x, lane = tid & 31, wid = tid >> 5;
    const int wm = wid >> 1, wn = wid & 1;

    if (tid < 128) bias_s[tid] = biasv[n0 + tid];

    const int lrow = tid >> 2, lch = tid & 3;
    auto load_tile = [&](int kt, int stage) {
#pragma unroll
        for (int i = 0; i < 2; i++) {
            int row = lrow + i * 64;
            size_t go = (size_t)row * U_ + kt * 32 + lch * 8;
            uint32_t so = sb + stage * 30720 + row * 80 + lch * 16;
            CPA16(so,         (const char*)g_a16 + 2 * ((size_t)m0 * U_ + go));
            CPA16(so + 10240, (const char*)wh    + 2 * ((size_t)n0 * U_ + go));
            CPA16(so + 20480, (const char*)wl    + 2 * ((size_t)n0 * U_ + go));
        }
        CPA_COMMIT();
    };

    float acc[2][8][4];
#pragma unroll
    for (int f = 0; f < 2; f++)
#pragma unroll
        for (int j = 0; j < 8; j++)
#pragma unroll
            for (int c = 0; c < 4; c++) acc[f][j][c] = 0.f;

    const uint32_t aoff = (uint32_t)((wm * 32 + (lane & 15)) * 80 + ((lane >> 4) * 8) * 2);
    const uint32_t boff = (uint32_t)((wn * 64 + (lane & 7) + ((lane >> 4) & 1) * 8) * 80
                                     + (((lane >> 3) & 1) * 8) * 2);

    load_tile(0, 0);
    CPA_WAIT0();
    __syncthreads();

    int buf = 0;
#pragma unroll 1
    for (int kt = 0; kt < 16; kt++) {
        if (kt < 15) load_tile(kt + 1, buf ^ 1);
        const uint32_t sbase = sb + buf * 30720;
#pragma unroll
        for (int ks = 0; ks < 2; ks++) {
            const uint32_t kb = (uint32_t)(ks * 32);
            uint32_t a[2][4], bh[4][4], bl[4][4];
            LDSM4(a[0], sbase + aoff + kb);
            LDSM4(a[1], sbase + aoff + kb + 16 * 80);
#pragma unroll
            for (int p = 0; p < 4; p++) {
                LDSM4(bh[p], sbase + 10240 + boff + kb + p * 16 * 80);
                LDSM4(bl[p], sbase + 20480 + boff + kb + p * 16 * 80);
            }
#pragma unroll
            for (int f = 0; f < 2; f++)
#pragma unroll
                for (int j = 0; j < 8; j++) {
                    uint32_t h0 = bh[j >> 1][(j & 1) * 2], h1 = bh[j >> 1][(j & 1) * 2 + 1];
                    uint32_t l0 = bl[j >> 1][(j & 1) * 2], l1 = bl[j >> 1][(j & 1) * 2 + 1];
                    MMA_F16(acc[f][j], a[f], h0, h1);
                    MMA_F16(acc[f][j], a[f], l0, l1);
                }
        }
        if (kt < 15) {
            CPA_WAIT0();
            __syncthreads();
            buf ^= 1;
        }
    }

#pragma unroll
    for (int f = 0; f < 2; f++) {
        const int r0 = m0 + wm * 32 + f * 16 + (lane >> 2);
#pragma unroll
        for (int j = 0; j < 8; j++) {
            const int cl = wn * 64 + j * 8 + (lane & 3) * 2;
            const int cg = n0 + cl;
            float2 o0 = make_float2(acc[f][j][0] + bias_s[cl], acc[f][j][1] + bias_s[cl + 1]);
            float2 o1 = make_float2(acc[f][j][2] + bias_s[cl], acc[f][j][3] + bias_s[cl + 1]);
            *(float2*)(Cout + (size_t)r0 * NC_ + cg)       = o0;
            *(float2*)(Cout + (size_t)(r0 + 8) * NC_ + cg) = o1;
        }
    }
}

__global__ __launch_bounds__(256) void gemm_mma(const float* __restrict__ bias) {
    extern __shared__ char smg[];
    gemm_tile(g_wh0, g_wl0, bias, g_xp, blockIdx.y * 128, blockIdx.x * 128,
              smg, smem_u32(smg));
}

// ---------------- split-SM wavefront recurrence, DECOUPLED barriers ----------------
// CTAs 0..63: layer 0 (CTA = 32b x 16u; K=512). CTAs 64..127: layer 1 (K=1024 over [y0|h1]).
// Per b-group: c0 (32 L0 arrivals), c1 (32 L1 arrivals). h0 triple-buffered.
__global__ __launch_bounds__(256, 1) void wave_rec(const float* __restrict__ b0v,
                                                   const float* __restrict__ b1v,
                                                   float* __restrict__ out1,
                                                   float* __restrict__ hl0,
                                                   float* __restrict__ hl1) {
    extern __shared__ char smb[];
    const uint32_t sb = smem_u32(smb);
    const int tid = threadIdx.x, lane = tid & 31, w = tid >> 5;
    const int bid = blockIdx.x;
    const bool isL1 = bid >= 64;
    const int lb = isL1 ? bid - 64 : bid;
    const int bg = lb >> 5, ug = lb & 31;
    const int b_base = bg * 32, u_base = ug * 16;
    unsigned* c0 = &g_bars[(bg * 2 + 0) * 32];
    unsigned* c1 = &g_bars[(bg * 2 + 1) * 32];

    const int nl = lane >> 2, kq = (lane & 3) * 2;
    const int m = lane >> 2, n0r = (lane & 3) * 2;
    const int b_loc = tid >> 3;           // 0..31
    const int u0 = (tid & 7) * 2;         // 0..14
    const int b_glob = b_base + b_loc;

    if (!isL1) {
        // ================= LAYER 0 =================
        const int kbase = w * 64;
        uint32_t rb[6][4][2];
#pragma unroll
        for (int nt = 0; nt < 6; nt++) {
            int ncol = nt * 8 + nl;
            int g = ncol >> 4, ul = ncol & 15;
            const __half* rp = g_r0 + ((size_t)(g * 512 + u_base + ul)) * 512;
#pragma unroll
            for (int ks = 0; ks < 4; ks++) {
                int k0 = kbase + ks * 16 + kq;
                rb[nt][ks][0] = *(const uint32_t*)(rp + k0);
                rb[nt][ks][1] = *(const uint32_t*)(rp + k0 + 8);
            }
        }

        float bz[2], brr[2], bhhc[2], xz[2], xr[2], xh[2], hown[2];
        const float* xpp = g_xp + (size_t)b_glob * T_ * NC_;
#pragma unroll
        for (int j = 0; j < 2; j++) {
            int ugl = u_base + u0 + j;
            bz[j]   = b0v[NC_ + ugl];
            brr[j]  = b0v[NC_ + U_ + ugl];
            bhhc[j] = b0v[NC_ + 2 * U_ + ugl];
            xz[j] = __ldg(xpp + ugl);
            xr[j] = __ldg(xpp + U_ + ugl);
            xh[j] = __ldg(xpp + 2 * U_ + ugl);
            hown[j] = 0.0f;
        }
        float* red = (float*)(smb + 33280);
        const uint32_t aoff = sb + (uint32_t)((lane & 15) * 1040 + (lane >> 4) * 16 + kbase * 2);

        int pw = 0, pr = 2;    // write buf s%3, read buf (s-1)%3
        for (int s = 0; s < T_; s++) {
            // wait: own group finished s-1; L1 finished s-2 (buffer free)
            if (tid == 0 && s >= 1) {
                bar_poll(c0, 32u * (unsigned)s);
                if (s >= 3) bar_poll(c1, 32u * (unsigned)(s - 2));
            }
            __syncthreads();

            if (s == 0) {
                for (int i = tid; i < 2080; i += 256)
                    ((uint4*)smb)[i] = make_uint4(0u, 0u, 0u, 0u);
            } else {
                const __half* hg = g_hx0[pr];
#pragma unroll
                for (int i = 0; i < 8; i++) {
                    int c = tid * 8 + i;
                    int row = c >> 6, off = c & 63;
                    CPA16(sb + row * 1040 + off * 16,
                          (const char*)(hg + (size_t)(b_base + row) * U_ + off * 8));
                }
                CPA_COMMIT();
                CPA_WAIT0();
            }
            __syncthreads();

            float acc[2][6][4];
#pragma unroll
            for (int mt = 0; mt < 2; mt++)
#pragma unroll
                for (int nt = 0; nt < 6; nt++)
#pragma unroll
                    for (int c = 0; c < 4; c++) acc[mt][nt][c] = 0.f;
#pragma unroll
            for (int ks = 0; ks < 4; ks++) {
                uint32_t a0[4], a1[4];
                LDSM4(a0, aoff + ks * 32);
                LDSM4(a1, aoff + 16 * 1040 + ks * 32);
#pragma unroll
                for (int nt = 0; nt < 6; nt++) {
                    MMA_F16(acc[0][nt], a0, rb[nt][ks][0], rb[nt][ks][1]);
                    MMA_F16(acc[1][nt], a1, rb[nt][ks][0], rb[nt][ks][1]);
                }
            }
#pragma unroll
            for (int mt = 0; mt < 2; mt++)
#pragma unroll
                for (int nt = 0; nt < 6; nt++) {
                    float* r0p = red + (size_t)(w * 32 + mt * 16 + m) * 50 + nt * 8 + n0r;
                    *(float2*)r0p = make_float2(acc[mt][nt][0], acc[mt][nt][1]);
                    *(float2*)(r0p + 8 * 50) = make_float2(acc[mt][nt][2], acc[mt][nt][3]);
                }
            __syncthreads();

#pragma unroll
            for (int j = 0; j < 2; j++) {
                int u_loc = u0 + j;
                float s0 = 0.f, s1 = 0.f, s2 = 0.f;
#pragma unroll
                for (int ww = 0; ww < 8; ww++) {
                    const float* rr = red + (size_t)(ww * 32 + b_loc) * 50;
                    s0 += rr[u_loc];
                    s1 += rr[16 + u_loc];
                    s2 += rr[32 + u_loc];
                }
                float z  = fsig(xz[j] + s0 + bz[j]);
                float r  = fsig(xr[j] + s1 + brr[j]);
                float hh = ftanh(xh[j] + r * (s2 + bhhc[j]));
                float hn = z * hown[j] + (1.0f - z) * hh;
                hown[j] = hn;
                STG_H16(&g_hx0[pw][(size_t)b_glob * U_ + u_base + u_loc],
                        __half_as_ushort(__float2half(hn)));
                if (s == T_ - 1) hl0[(size_t)b_glob * U_ + u_base + u_loc] = hn;
            }
            if (s + 1 < T_) {
#pragma unroll
                for (int j = 0; j < 2; j++) {
                    int ugl = u_base + u0 + j;
                    xz[j] = __ldg(xpp + (size_t)(s + 1) * NC_ + ugl);
                    xr[j] = __ldg(xpp + (size_t)(s + 1) * NC_ + U_ + ugl);
                    xh[j] = __ldg(xpp + (size_t)(s + 1) * NC_ + 2 * U_ + ugl);
                }
            }
            __syncthreads();
            if (tid == 0) bar_arrive(c0);
            pr = pw;
            pw = (pw == 2) ? 0 : pw + 1;
        }
    } else {
        // ================= LAYER 1 =================
        const int kbaseA = w * 128;
        const __half* WZ = (w < 4) ? g_wh1 : g_r1;
        const int kW = (w < 4) ? kbaseA : kbaseA - 512;

        uint32_t rzr[4][8][2];
#pragma unroll
        for (int nt = 0; nt < 4; nt++) {
            int ncol = nt * 8 + nl;
            int g = ncol >> 4, ul = ncol & 15;
            const __half* rp = WZ + ((size_t)(g * 512 + u_base + ul)) * 512;
#pragma unroll
            for (int ks = 0; ks < 8; ks++) {
                int k0 = kW + ks * 16 + kq;
                rzr[nt][ks][0] = *(const uint32_t*)(rp + k0);
                rzr[nt][ks][1] = *(const uint32_t*)(rp + k0 + 8);
            }
        }
        uint32_t rhh[2][8][2];
#pragma unroll
        for (int nt = 0; nt < 2; nt++) {
            int ul = nt * 8 + nl;
            const __half* rp = WZ + ((size_t)(1024 + u_base + ul)) * 512;
#pragma unroll
            for (int ks = 0; ks < 8; ks++) {
                int k0 = kW + ks * 16 + kq;
                rhh[nt][ks][0] = *(const uint32_t*)(rp + k0);
                rhh[nt][ks][1] = *(const uint32_t*)(rp + k0 + 8);
            }
        }

        float cz[2], cr[2], bih[2], bhh2[2], hown[2];
#pragma unroll
        for (int j = 0; j < 2; j++) {
            int ugl = u_base + u0 + j;
            cz[j]   = b1v[ugl] + b1v[NC_ + ugl];
            cr[j]   = b1v[U_ + ugl] + b1v[NC_ + U_ + ugl];
            bih[j]  = b1v[2 * U_ + ugl];
            bhh2[j] = b1v[NC_ + 2 * U_ + ugl];
            hown[j] = 0.0f;
        }
        float* red = (float*)(smb + 66048);      // [8][32][52]
        const uint32_t aoff = sb + (uint32_t)((lane & 15) * 2064 + (lane >> 4) * 16 + kbaseA * 2);

        int ph = 0;    // (s-1)%3
        for (int s = 1; s <= T_; s++) {
            // wait: L0 finished step s-1; own group finished s-1
            if (tid == 0) {
                bar_poll(c0, 32u * (unsigned)s);
                if (s >= 2) bar_poll(c1, 32u * (unsigned)(s - 1));
            }
            __syncthreads();

            if (s == 1) {
                for (int i = tid; i < 2048; i += 256) {
                    int row = i >> 6, off = i & 63;
                    *(uint4*)(smb + row * 2064 + 1024 + off * 16) =
                        make_uint4(0u, 0u, 0u, 0u);
                }
            }
            {
                const __half* hy = g_hx0[ph];
#pragma unroll
                for (int i = 0; i < 8; i++) {
                    int c = tid * 8 + i;
                    int row = c >> 6, off = c & 63;
                    CPA16(sb + row * 2064 + off * 16,
                          (const char*)(hy + (size_t)(b_base + row) * U_ + off * 8));
                }
                if (s >= 2) {
                    const __half* hh1 = g_hx1[s & 1];
#pragma unroll
                    for (int i = 0; i < 8; i++) {
                        int c = tid * 8 + i;
                        int row = c >> 6, off = c & 63;
                        CPA16(sb + row * 2064 + 1024 + off * 16,
                              (const char*)(hh1 + (size_t)(b_base + row) * U_ + off * 8));
                    }
                }
                CPA_COMMIT();
                CPA_WAIT0();
            }
            __syncthreads();

            float acc[2][6][4];
#pragma unroll
            for (int mt = 0; mt < 2; mt++)
#pragma unroll
                for (int nt = 0; nt < 6; nt++)
#pragma unroll
                    for (int c = 0; c < 4; c++) acc[mt][nt][c] = 0.f;
#pragma unroll
            for (int ks = 0; ks < 8; ks++) {
                uint32_t a0[4], a1[4];
                LDSM4(a0, aoff + ks * 32);
                LDSM4(a1, aoff + 16 * 2064 + ks * 32);
#pragma unroll
                for (int nt = 0; nt < 4; nt++) {
                    MMA_F16(acc[0][nt], a0, rzr[nt][ks][0], rzr[nt][ks][1]);
                    MMA_F16(acc[1][nt], a1, rzr[nt][ks][0], rzr[nt][ks][1]);
                }
#pragma unroll
                for (int nt = 0; nt < 2; nt++) {
                    MMA_F16(acc[0][4 + nt], a0, rhh[nt][ks][0], rhh[nt][ks][1]);
                    MMA_F16(acc[1][4 + nt], a1, rhh[nt][ks][0], rhh[nt][ks][1]);
                }
            }
#pragma unroll
            for (int mt = 0; mt < 2; mt++) {
#pragma unroll
                for (int nt = 0; nt < 4; nt++) {
                    float* r0p = red + (size_t)(w * 32 + mt * 16 + m) * 52 + nt * 8 + n0r;
                    *(float2*)r0p = make_float2(acc[mt][nt][0], acc[mt][nt][1]);
                    *(float2*)(r0p + 8 * 52) = make_float2(acc[mt][nt][2], acc[mt][nt][3]);
                }
#pragma unroll
                for (int nt = 0; nt < 2; nt++) {
                    float* r0p = red + (size_t)(w * 32 + mt * 16 + m) * 52 + 32 + nt * 8 + n0r;
                    *(float2*)r0p = make_float2(acc[mt][4 + nt][0], acc[mt][4 + nt][1]);
                    *(float2*)(r0p + 8 * 52) = make_float2(acc[mt][4 + nt][2], acc[mt][4 + nt][3]);
                }
            }
            __syncthreads();

#pragma unroll
            for (int j = 0; j < 2; j++) {
                int u_loc = u0 + j;
                float zv = 0.f, rv = 0.f, pv = 0.f, qv = 0.f;
#pragma unroll
                for (int ww = 0; ww < 8; ww++) {
                    const float* rr = red + (size_t)(ww * 32 + b_loc) * 52;
                    zv += rr[u_loc];
                    rv += rr[16 + u_loc];
                    if (ww < 4) pv += rr[32 + u_loc];
                    else        qv += rr[32 + u_loc];
                }
                float z  = fsig(zv + cz[j]);
                float r  = fsig(rv + cr[j]);
                float hh = ftanh(pv + bih[j] + r * (qv + bhh2[j]));
                float hn = z * hown[j] + (1.0f - z) * hh;
                hown[j] = hn;
                out1[(size_t)b_glob * T_ * U_ + (size_t)(s - 1) * U_ + u_base + u_loc] = hn;
                if (s <= T_ - 1)
                    STG_H16(&g_hx1[(s - 1) & 1][(size_t)b_glob * U_ + u_base + u_loc],
                            __half_as_ushort(__float2half(hn)));
                if (s == T_) hl1[(size_t)b_glob * U_ + u_base + u_loc] = hn;
            }
            __syncthreads();
            if (tid == 0) bar_arrive(c1);
            ph = (ph == 2) ? 0 : ph + 1;
        }
    }
}

// ---------------- launcher ----------------
extern "C" void kernel_launch(void* const* d_in, const int* in_sizes, int n_in,
                              void* d_out, int out_size) {
    const float* x  = (const float*)d_in[0];
    const float* W0 = (const float*)d_in[1];
    const float* R0 = (const float*)d_in[2];
    const float* b0 = (const float*)d_in[3];
    const float* W1 = (const float*)d_in[4];
    const float* R1 = (const float*)d_in[5];
    const float* b1 = (const float*)d_in[6];

    float* out  = (float*)d_out;
    float* out1 = out;                               // [64,1024,512]
    float* h0   = out + (size_t)B_ * T_ * U_;        // [64,512]
    float* h1   = h0 + (size_t)B_ * U_;              // [64,512]

    cudaFuncSetAttribute(wave_rec, cudaFuncAttributeMaxDynamicSharedMemorySize,
                         SMEM_WAVE);
    cudaFuncSetAttribute(gemm_mma, cudaFuncAttributeMaxDynamicSharedMemorySize,
                         SMEM_GEMM);

    prep_weights<<<NC_ * U_ / 256, 256>>>(W0, W1, R0, R1);   // 0
    split_x<<<4096, 256>>>(x);                               // 1
    dim3 g0(12, 512);
    gemm_mma<<<g0, 256, SMEM_GEMM>>>(b0);                    // 2
    wave_rec<<<128, 256, SMEM_WAVE>>>(b0, b1, out1, h0, h1); // 3 -> ncu
}

// round 15
// speedup vs baseline: 1.4366x; 1.0229x over previous
#include <cuda_runtime.h>
#include <cuda_fp16.h>
#include <cstdint>

#define B_  64
#define T_  1024
#define U_  512
#define NC_ 1536
#define M_  (B_ * T_)          // 65536
#define SMEM_WAVE 121856       // forces 1 CTA/SM for the persistent grid
#define SMEM_GEMM 61952

// ---------------- device scratch ----------------
__device__ float    g_xp [(size_t)M_ * NC_];      // layer-0 input projections
__device__ unsigned g_bars[4 * 32];               // [bg*2+layer] counters, 128B apart
__device__ __half   g_a16[(size_t)M_ * U_];       // x (fp16) [m][k]
__device__ __half   g_wh0[(size_t)NC_ * U_];      // W0^T hi [n][k]
__device__ __half   g_wl0[(size_t)NC_ * U_];      // W0^T lo
__device__ __half   g_wh1[(size_t)NC_ * U_];      // W1^T fp16 [n][k]
__device__ __half   g_r0 [(size_t)NC_ * U_];      // R0^T fp16 [n][k]
__device__ __half   g_r1 [(size_t)NC_ * U_];      // R1^T fp16
__device__ __half   g_hx0[3][B_ * U_];            // h0 exchange, triple buffered
__device__ __half   g_hx1[2][B_ * U_];            // h1 exchange, double buffered

// ---------------- helpers ----------------
static __device__ __forceinline__ float fsig(float x) {
    return __fdividef(1.0f, 1.0f + __expf(-x));
}
static __device__ __forceinline__ float ftanh(float x) {
    return 1.0f - __fdividef(2.0f, __expf(2.0f * x) + 1.0f);
}
static __device__ __forceinline__ uint32_t smem_u32(const void* p) {
    uint32_t a;
    asm("{ .reg .u64 t; cvta.to.shared.u64 t, %1; cvt.u32.u64 %0, t; }"
        : "=r"(a) : "l"(p));
    return a;
}
#define LDSM4(r, addr) \
    asm volatile("ldmatrix.sync.aligned.m8n8.x4.shared.b16 {%0,%1,%2,%3}, [%4];" \
        : "=r"((r)[0]), "=r"((r)[1]), "=r"((r)[2]), "=r"((r)[3]) : "r"(addr))
#define MMA_F16(d, a, b0v, b1v) \
    asm volatile("mma.sync.aligned.m16n8k16.row.col.f32.f16.f16.f32 " \
        "{%0,%1,%2,%3}, {%4,%5,%6,%7}, {%8,%9}, {%0,%1,%2,%3};" \
        : "+f"((d)[0]), "+f"((d)[1]), "+f"((d)[2]), "+f"((d)[3]) \
        : "r"((a)[0]), "r"((a)[1]), "r"((a)[2]), "r"((a)[3]), "r"(b0v), "r"(b1v))
#define CPA16(dst, src) \
    asm volatile("cp.async.cg.shared.global [%0], [%1], 16;" :: "r"(dst), "l"(src))
#define CPA_COMMIT() asm volatile("cp.async.commit_group;")
#define CPA_WAIT0()  asm volatile("cp.async.wait_group 0;" ::: "memory")
#define STG_H16(p, v) \
    asm volatile("st.global.cg.u16 [%0], %1;" :: "l"(p), "h"(v) : "memory")

static __device__ __forceinline__ void bar_arrive(unsigned* p) {
    asm volatile("red.release.gpu.global.add.u32 [%0], 1;" :: "l"(p) : "memory");
}
static __device__ __forceinline__ void bar_poll(unsigned* p, unsigned target) {
    unsigned cur;
    do {
        asm volatile("ld.acquire.gpu.global.u32 %0, [%1];"
                     : "=r"(cur) : "l"(p) : "memory");
    } while (cur < target);
}
static __device__ __forceinline__ unsigned ldcg_u32(const __half* p) {
    unsigned v;
    asm volatile("ld.global.cg.u32 %0, [%1];" : "=r"(v) : "l"(p) : "memory");
    return v;
}

// ---------------- prep: weight conversions ----------------
__global__ void prep_weights(const float* __restrict__ W0, const float* __restrict__ W1,
                             const float* __restrict__ R0, const float* __restrict__ R1) {
    if (blockIdx.x == 0 && threadIdx.x < 4) g_bars[threadIdx.x * 32] = 0u;
    int i = blockIdx.x * blockDim.x + threadIdx.x;
    if (i < NC_ * U_) {
        int n = i >> 9, k = i & 511;
        float v0 = W0[(size_t)k * NC_ + n];
        __half h0 = __float2half(v0);
        g_wh0[i] = h0;
        g_wl0[i] = __float2half(v0 - __half2float(h0));
        g_wh1[i] = __float2half(W1[(size_t)k * NC_ + n]);
        g_r0[i]  = __float2half(R0[(size_t)k * NC_ + n]);
        g_r1[i]  = __float2half(R1[(size_t)k * NC_ + n]);
    }
}

__global__ void split_x(const float* __restrict__ src) {
    size_t n = (size_t)M_ * U_;
    for (size_t i = (size_t)blockIdx.x * blockDim.x + threadIdx.x; i < n;
         i += (size_t)gridDim.x * blockDim.x)
        g_a16[i] = __float2half(src[i]);
}

// ---------------- layer-0 projection GEMM (proven core) ----------------
static __device__ __forceinline__ void gemm_tile(const __half* __restrict__ wh,
                                                 const __half* __restrict__ wl,
                                                 const float* __restrict__ biasv,
                                                 float* __restrict__ Cout,
                                                 int m0, int n0, char* sm, uint32_t sb) {
    float* bias_s = (float*)(sm + 61440);
    const int tid = threadIdx.x, lane = tid & 31, wid = tid >> 5;
    const int wm = wid >> 1, wn = wid & 1;

    if (tid < 128) bias_s[tid] = biasv[n0 + tid];

    const int lrow = tid >> 2, lch = tid & 3;
    auto load_tile = [&](int kt, int stage) {
#pragma unroll
        for (int i = 0; i < 2; i++) {
            int row = lrow + i * 64;
            size_t go = (size_t)row * U_ + kt * 32 + lch * 8;
            uint32_t so = sb + stage * 30720 + row * 80 + lch * 16;
            CPA16(so,         (const char*)g_a16 + 2 * ((size_t)m0 * U_ + go));
            CPA16(so + 10240, (const char*)wh    + 2 * ((size_t)n0 * U_ + go));
            CPA16(so + 20480, (const char*)wl    + 2 * ((size_t)n0 * U_ + go));
        }
        CPA_COMMIT();
    };

    float acc[2][8][4];
#pragma unroll
    for (int f = 0; f < 2; f++)
#pragma unroll
        for (int j = 0; j < 8; j++)
#pragma unroll
            for (int c = 0; c < 4; c++) acc[f][j][c] = 0.f;

    const uint32_t aoff = (uint32_t)((wm * 32 + (lane & 15)) * 80 + ((lane >> 4) * 8) * 2);
    const uint32_t boff = (uint32_t)((wn * 64 + (lane & 7) + ((lane >> 4) & 1) * 8) * 80
                                     + (((lane >> 3) & 1) * 8) * 2);

    load_tile(0, 0);
    CPA_WAIT0();
    __syncthreads();

    int buf = 0;
#pragma unroll 1
    for (int kt = 0; kt < 16; kt++) {
        if (kt < 15) load_tile(kt + 1, buf ^ 1);
        const uint32_t sbase = sb + buf * 30720;
#pragma unroll
        for (int ks = 0; ks < 2; ks++) {
            const uint32_t kb = (uint32_t)(ks * 32);
            uint32_t a[2][4], bh[4][4], bl[4][4];
            LDSM4(a[0], sbase + aoff + kb);
            LDSM4(a[1], sbase + aoff + kb + 16 * 80);
#pragma unroll
            for (int p = 0; p < 4; p++) {
                LDSM4(bh[p], sbase + 10240 + boff + kb + p * 16 * 80);
                LDSM4(bl[p], sbase + 20480 + boff + kb + p * 16 * 80);
            }
#pragma unroll
            for (int f = 0; f < 2; f++)
#pragma unroll
                for (int j = 0; j < 8; j++) {
                    uint32_t h0 = bh[j >> 1][(j & 1) * 2], h1 = bh[j >> 1][(j & 1) * 2 + 1];
                    uint32_t l0 = bl[j >> 1][(j & 1) * 2], l1 = bl[j >> 1][(j & 1) * 2 + 1];
                    MMA_F16(acc[f][j], a[f], h0, h1);
                    MMA_F16(acc[f][j], a[f], l0, l1);
                }
        }
        if (kt < 15) {
            CPA_WAIT0();
            __syncthreads();
            buf ^= 1;
        }
    }

#pragma unroll
    for (int f = 0; f < 2; f++) {
        const int r0 = m0 + wm * 32 + f * 16 + (lane >> 2);
#pragma unroll
        for (int j = 0; j < 8; j++) {
            const int cl = wn * 64 + j * 8 + (lane & 3) * 2;
            const int cg = n0 + cl;
            float2 o0 = make_float2(acc[f][j][0] + bias_s[cl], acc[f][j][1] + bias_s[cl + 1]);
            float2 o1 = make_float2(acc[f][j][2] + bias_s[cl], acc[f][j][3] + bias_s[cl + 1]);
            *(float2*)(Cout + (size_t)r0 * NC_ + cg)       = o0;
            *(float2*)(Cout + (size_t)(r0 + 8) * NC_ + cg) = o1;
        }
    }
}

__global__ __launch_bounds__(256) void gemm_mma(const float* __restrict__ bias) {
    extern __shared__ char smg[];
    gemm_tile(g_wh0, g_wl0, bias, g_xp, blockIdx.y * 128, blockIdx.x * 128,
              smg, smem_u32(smg));
}

// ---------------- split-SM wavefront, direct-LDG fragments, 2 syncs/step ----------------
// CTAs 0..63: layer 0 (CTA = 32b x 16u; K=512). CTAs 64..127: layer 1 (K=1024 over [y0|h1]).
__global__ __launch_bounds__(256, 1) void wave_rec(const float* __restrict__ b0v,
                                                   const float* __restrict__ b1v,
                                                   float* __restrict__ out1,
                                                   float* __restrict__ hl0,
                                                   float* __restrict__ hl1) {
    extern __shared__ char smb[];
    float* red = (float*)smb;
    const int tid = threadIdx.x, lane = tid & 31, w = tid >> 5;
    const int bid = blockIdx.x;
    const bool isL1 = bid >= 64;
    const int lb = isL1 ? bid - 64 : bid;
    const int bg = lb >> 5, ug = lb & 31;
    const int b_base = bg * 32, u_base = ug * 16;
    unsigned* c0 = &g_bars[(bg * 2 + 0) * 32];
    unsigned* c1 = &g_bars[(bg * 2 + 1) * 32];

    const int nl = lane >> 2, kq = (lane & 3) * 2;
    const int m = lane >> 2, n0r = (lane & 3) * 2;
    const int r0 = lane >> 2, cb = (lane & 3) * 2;     // A-fragment coords
    const int b_loc = tid >> 3;           // 0..31
    const int u0 = (tid & 7) * 2;         // 0..14
    const int b_glob = b_base + b_loc;

    if (!isL1) {
        // ================= LAYER 0 =================
        const int kbase = w * 64;
        uint32_t rb[6][4][2];
#pragma unroll
        for (int nt = 0; nt < 6; nt++) {
            int ncol = nt * 8 + nl;
            int g = ncol >> 4, ul = ncol & 15;
            const __half* rp = g_r0 + ((size_t)(g * 512 + u_base + ul)) * 512;
#pragma unroll
            for (int ks = 0; ks < 4; ks++) {
                int k0 = kbase + ks * 16 + kq;
                rb[nt][ks][0] = *(const uint32_t*)(rp + k0);
                rb[nt][ks][1] = *(const uint32_t*)(rp + k0 + 8);
            }
        }

        float bz[2], brr[2], bhhc[2], xz[2], xr[2], xh[2], hown[2];
        const float* xpp = g_xp + (size_t)b_glob * T_ * NC_;
#pragma unroll
        for (int j = 0; j < 2; j++) {
            int ugl = u_base + u0 + j;
            bz[j]   = b0v[NC_ + ugl];
            brr[j]  = b0v[NC_ + U_ + ugl];
            bhhc[j] = b0v[NC_ + 2 * U_ + ugl];
            xz[j] = __ldg(xpp + ugl);
            xr[j] = __ldg(xpp + U_ + ugl);
            xh[j] = __ldg(xpp + 2 * U_ + ugl);
            hown[j] = 0.0f;
        }
        const int cc = kbase + cb;

        int pw = 0, pr = 2;
        for (int s = 0; s < T_; s++) {
            // all threads poll: own group at s; L1 lag (buffer free)
            if (s >= 1) {
                bar_poll(c0, 32u * (unsigned)s);
                if (s >= 3) bar_poll(c1, 32u * (unsigned)(s - 2));
            }

            // A fragments direct from global
            uint32_t af[2][4][4];
            if (s == 0) {
#pragma unroll
                for (int mt = 0; mt < 2; mt++)
#pragma unroll
                    for (int ks = 0; ks < 4; ks++)
#pragma unroll
                        for (int c = 0; c < 4; c++) af[mt][ks][c] = 0u;
            } else {
                const __half* hg = g_hx0[pr] + (size_t)b_base * U_;
#pragma unroll
                for (int mt = 0; mt < 2; mt++)
#pragma unroll
                    for (int ks = 0; ks < 4; ks++) {
                        const __half* hp = hg + (size_t)(mt * 16 + r0) * U_ + cc + ks * 16;
                        af[mt][ks][0] = ldcg_u32(hp);
                        af[mt][ks][1] = ldcg_u32(hp + 8 * U_);
                        af[mt][ks][2] = ldcg_u32(hp + 8);
                        af[mt][ks][3] = ldcg_u32(hp + 8 * U_ + 8);
                    }
            }

            float acc[2][6][4];
#pragma unroll
            for (int mt = 0; mt < 2; mt++)
#pragma unroll
                for (int nt = 0; nt < 6; nt++)
#pragma unroll
                    for (int c = 0; c < 4; c++) acc[mt][nt][c] = 0.f;
#pragma unroll
            for (int ks = 0; ks < 4; ks++)
#pragma unroll
                for (int nt = 0; nt < 6; nt++) {
                    MMA_F16(acc[0][nt], af[0][ks], rb[nt][ks][0], rb[nt][ks][1]);
                    MMA_F16(acc[1][nt], af[1][ks], rb[nt][ks][0], rb[nt][ks][1]);
                }
#pragma unroll
            for (int mt = 0; mt < 2; mt++)
#pragma unroll
                for (int nt = 0; nt < 6; nt++) {
                    float* r0p = red + (size_t)(w * 32 + mt * 16 + m) * 50 + nt * 8 + n0r;
                    *(float2*)r0p = make_float2(acc[mt][nt][0], acc[mt][nt][1]);
                    *(float2*)(r0p + 8 * 50) = make_float2(acc[mt][nt][2], acc[mt][nt][3]);
                }
            __syncthreads();

#pragma unroll
            for (int j = 0; j < 2; j++) {
                int u_loc = u0 + j;
                float s0 = 0.f, s1 = 0.f, s2 = 0.f;
#pragma unroll
                for (int ww = 0; ww < 8; ww++) {
                    const float* rr = red + (size_t)(ww * 32 + b_loc) * 50;
                    s0 += rr[u_loc];
                    s1 += rr[16 + u_loc];
                    s2 += rr[32 + u_loc];
                }
                float z  = fsig(xz[j] + s0 + bz[j]);
                float r  = fsig(xr[j] + s1 + brr[j]);
                float hh = ftanh(xh[j] + r * (s2 + bhhc[j]));
                float hn = z * hown[j] + (1.0f - z) * hh;
                hown[j] = hn;
                STG_H16(&g_hx0[pw][(size_t)b_glob * U_ + u_base + u_loc],
                        __half_as_ushort(__float2half(hn)));
                if (s == T_ - 1) hl0[(size_t)b_glob * U_ + u_base + u_loc] = hn;
            }
            if (s + 1 < T_) {
#pragma unroll
                for (int j = 0; j < 2; j++) {
                    int ugl = u_base + u0 + j;
                    xz[j] = __ldg(xpp + (size_t)(s + 1) * NC_ + ugl);
                    xr[j] = __ldg(xpp + (size_t)(s + 1) * NC_ + U_ + ugl);
                    xh[j] = __ldg(xpp + (size_t)(s + 1) * NC_ + 2 * U_ + ugl);
                }
            }
            __syncthreads();
            if (tid == 0) bar_arrive(c0);
            pr = pw;
            pw = (pw == 2) ? 0 : pw + 1;
        }
    } else {
        // ================= LAYER 1 =================
        const int kbaseA = w * 128;
        const __half* WZ = (w < 4) ? g_wh1 : g_r1;
        const int kW = (w < 4) ? kbaseA : kbaseA - 512;

        uint32_t rzr[4][8][2];
#pragma unroll
        for (int nt = 0; nt < 4; nt++) {
            int ncol = nt * 8 + nl;
            int g = ncol >> 4, ul = ncol & 15;
            const __half* rp = WZ + ((size_t)(g * 512 + u_base + ul)) * 512;
#pragma unroll
            for (int ks = 0; ks < 8; ks++) {
                int k0 = kW + ks * 16 + kq;
                rzr[nt][ks][0] = *(const uint32_t*)(rp + k0);
                rzr[nt][ks][1] = *(const uint32_t*)(rp + k0 + 8);
            }
        }
        uint32_t rhh[2][8][2];
#pragma unroll
        for (int nt = 0; nt < 2; nt++) {
            int ul = nt * 8 + nl;
            const __half* rp = WZ + ((size_t)(1024 + u_base + ul)) * 512;
#pragma unroll
            for (int ks = 0; ks < 8; ks++) {
                int k0 = kW + ks * 16 + kq;
                rhh[nt][ks][0] = *(const uint32_t*)(rp + k0);
                rhh[nt][ks][1] = *(const uint32_t*)(rp + k0 + 8);
            }
        }

        float cz[2], cr[2], bih[2], bhh2[2], hown[2];
#pragma unroll
        for (int j = 0; j < 2; j++) {
            int ugl = u_base + u0 + j;
            cz[j]   = b1v[ugl] + b1v[NC_ + ugl];
            cr[j]   = b1v[U_ + ugl] + b1v[NC_ + U_ + ugl];
            bih[j]  = b1v[2 * U_ + ugl];
            bhh2[j] = b1v[NC_ + 2 * U_ + ugl];
            hown[j] = 0.0f;
        }
        const int cc = ((w < 4) ? kbaseA : kbaseA - 512) + cb;

        int ph = 0;
        for (int s = 1; s <= T_; s++) {
            bar_poll(c0, 32u * (unsigned)s);
            if (s >= 2) bar_poll(c1, 32u * (unsigned)(s - 1));

            const __half* asrc = ((w < 4) ? g_hx0[ph] : g_hx1[s & 1])
                                 + (size_t)b_base * U_;
            const bool azero = (w >= 4 && s == 1);

            float acc[2][6][4];
#pragma unroll
            for (int mt = 0; mt < 2; mt++)
#pragma unroll
                for (int nt = 0; nt < 6; nt++)
#pragma unroll
                    for (int c = 0; c < 4; c++) acc[mt][nt][c] = 0.f;

#pragma unroll
            for (int half = 0; half < 2; half++) {
                uint32_t af[2][4][4];
#pragma unroll
                for (int mt = 0; mt < 2; mt++)
#pragma unroll
                    for (int kk = 0; kk < 4; kk++) {
                        int ks = half * 4 + kk;
                        if (azero) {
                            af[mt][kk][0] = af[mt][kk][1] = 0u;
                            af[mt][kk][2] = af[mt][kk][3] = 0u;
                        } else {
                            const __half* hp = asrc + (size_t)(mt * 16 + r0) * U_ + cc + ks * 16;
                            af[mt][kk][0] = ldcg_u32(hp);
                            af[mt][kk][1] = ldcg_u32(hp + 8 * U_);
                            af[mt][kk][2] = ldcg_u32(hp + 8);
                            af[mt][kk][3] = ldcg_u32(hp + 8 * U_ + 8);
                        }
                    }
#pragma unroll
                for (int kk = 0; kk < 4; kk++) {
                    int ks = half * 4 + kk;
#pragma unroll
                    for (int nt = 0; nt < 4; nt++) {
                        MMA_F16(acc[0][nt], af[0][kk], rzr[nt][ks][0], rzr[nt][ks][1]);
                        MMA_F16(acc[1][nt], af[1][kk], rzr[nt][ks][0], rzr[nt][ks][1]);
                    }
#pragma unroll
                    for (int nt = 0; nt < 2; nt++) {
                        MMA_F16(acc[0][4 + nt], af[0][kk], rhh[nt][ks][0], rhh[nt][ks][1]);
                        MMA_F16(acc[1][4 + nt], af[1][kk], rhh[nt][ks][0], rhh[nt][ks][1]);
                    }
                }
            }

#pragma unroll
            for (int mt = 0; mt < 2; mt++) {
#pragma unroll
                for (int nt = 0; nt < 4; nt++) {
                    float* r0p = red + (size_t)(w * 32 + mt * 16 + m) * 52 + nt * 8 + n0r;
                    *(float2*)r0p = make_float2(acc[mt][nt][0], acc[mt][nt][1]);
                    *(float2*)(r0p + 8 * 52) = make_float2(acc[mt][nt][2], acc[mt][nt][3]);
                }
#pragma unroll
                for (int nt = 0; nt < 2; nt++) {
                    float* r0p = red + (size_t)(w * 32 + mt * 16 + m) * 52 + 32 + nt * 8 + n0r;
                    *(float2*)r0p = make_float2(acc[mt][4 + nt][0], acc[mt][4 + nt][1]);
                    *(float2*)(r0p + 8 * 52) = make_float2(acc[mt][4 + nt][2], acc[mt][4 + nt][3]);
                }
            }
            __syncthreads();

#pragma unroll
            for (int j = 0; j < 2; j++) {
                int u_loc = u0 + j;
                float zv = 0.f, rv = 0.f, pv = 0.f, qv = 0.f;
#pragma unroll
                for (int ww = 0; ww < 8; ww++) {
                    const float* rr = red + (size_t)(ww * 32 + b_loc) * 52;
                    zv += rr[u_loc];
                    rv += rr[16 + u_loc];
                    if (ww < 4) pv += rr[32 + u_loc];
                    else        qv += rr[32 + u_loc];
                }
                float z  = fsig(zv + cz[j]);
                float r  = fsig(rv + cr[j]);
                float hh = ftanh(pv + bih[j] + r * (qv + bhh2[j]));
                float hn = z * hown[j] + (1.0f - z) * hh;
                hown[j] = hn;
                out1[(size_t)b_glob * T_ * U_ + (size_t)(s - 1) * U_ + u_base + u_loc] = hn;
                if (s <= T_ - 1)
                    STG_H16(&g_hx1[(s - 1) & 1][(size_t)b_glob * U_ + u_base + u_loc],
                            __half_as_ushort(__float2half(hn)));
                if (s == T_) hl1[(size_t)b_glob * U_ + u_base + u_loc] = hn;
            }
            __syncthreads();
            if (tid == 0) bar_arrive(c1);
            ph = (ph == 2) ? 0 : ph + 1;
        }
    }
}

// ---------------- launcher ----------------
extern "C" void kernel_launch(void* const* d_in, const int* in_sizes, int n_in,
                              void* d_out, int out_size) {
    const float* x  = (const float*)d_in[0];
    const float* W0 = (const float*)d_in[1];
    const float* R0 = (const float*)d_in[2];
    const float* b0 = (const float*)d_in[3];
    const float* W1 = (const float*)d_in[4];
    const float* R1 = (const float*)d_in[5];
    const float* b1 = (const float*)d_in[6];

    float* out  = (float*)d_out;
    float* out1 = out;                               // [64,1024,512]
    float* h0   = out + (size_t)B_ * T_ * U_;        // [64,512]
    float* h1   = h0 + (size_t)B_ * U_;              // [64,512]

    cudaFuncSetAttribute(wave_rec, cudaFuncAttributeMaxDynamicSharedMemorySize,
                         SMEM_WAVE);
    cudaFuncSetAttribute(gemm_mma, cudaFuncAttributeMaxDynamicSharedMemorySize,
                         SMEM_GEMM);

    prep_weights<<<NC_ * U_ / 256, 256>>>(W0, W1, R0, R1);   // 0
    split_x<<<4096, 256>>>(x);                               // 1
    dim3 g0(12, 512);
    gemm_mma<<<g0, 256, SMEM_GEMM>>>(b0);                    // 2
    wave_rec<<<128, 256, SMEM_WAVE>>>(b0, b1, out1, h0, h1); // 3 -> ncu
}

// round 16
// speedup vs baseline: 1.5128x; 1.0531x over previous
#include <cuda_runtime.h>
#include <cuda_fp16.h>
#include <cstdint>

#define B_  64
#define T_  1024
#define U_  512
#define NC_ 1536
#define M_  (B_ * T_)          // 65536
#define SMEM_WAVE 121856       // forces 1 CTA/SM for the persistent grid
#define SMEM_GEMM 61952

// ---------------- device scratch ----------------
__device__ float    g_xp [(size_t)M_ * NC_];      // layer-0 input projections
__device__ unsigned g_bars[4 * 32];               // [bg*2+layer] counters, 128B apart
__device__ unsigned g_chunk[8 * 32];              // per-t-chunk production counters
__device__ __half   g_a16[(size_t)M_ * U_];       // x (fp16) [m][k]
__device__ __half   g_wh0[(size_t)NC_ * U_];      // W0^T hi [n][k]
__device__ __half   g_wl0[(size_t)NC_ * U_];      // W0^T lo
__device__ __half   g_wh1[(size_t)NC_ * U_];      // W1^T fp16 [n][k]
__device__ __half   g_r0 [(size_t)NC_ * U_];      // R0^T fp16 [n][k]
__device__ __half   g_r1 [(size_t)NC_ * U_];      // R1^T fp16
__device__ __half   g_hx0[3][B_ * U_];            // h0 exchange, triple buffered
__device__ __half   g_hx1[2][B_ * U_];            // h1 exchange, double buffered

// ---------------- helpers ----------------
static __device__ __forceinline__ float fsig(float x) {
    return __fdividef(1.0f, 1.0f + __expf(-x));
}
static __device__ __forceinline__ float ftanh(float x) {
    return 1.0f - __fdividef(2.0f, __expf(2.0f * x) + 1.0f);
}
static __device__ __forceinline__ uint32_t smem_u32(const void* p) {
    uint32_t a;
    asm("{ .reg .u64 t; cvta.to.shared.u64 t, %1; cvt.u32.u64 %0, t; }"
        : "=r"(a) : "l"(p));
    return a;
}
#define LDSM4(r, addr) \
    asm volatile("ldmatrix.sync.aligned.m8n8.x4.shared.b16 {%0,%1,%2,%3}, [%4];" \
        : "=r"((r)[0]), "=r"((r)[1]), "=r"((r)[2]), "=r"((r)[3]) : "r"(addr))
#define MMA_F16(d, a, b0v, b1v) \
    asm volatile("mma.sync.aligned.m16n8k16.row.col.f32.f16.f16.f32 " \
        "{%0,%1,%2,%3}, {%4,%5,%6,%7}, {%8,%9}, {%0,%1,%2,%3};" \
        : "+f"((d)[0]), "+f"((d)[1]), "+f"((d)[2]), "+f"((d)[3]) \
        : "r"((a)[0]), "r"((a)[1]), "r"((a)[2]), "r"((a)[3]), "r"(b0v), "r"(b1v))
#define CPA16(dst, src) \
    asm volatile("cp.async.cg.shared.global [%0], [%1], 16;" :: "r"(dst), "l"(src))
#define CPA_COMMIT() asm volatile("cp.async.commit_group;")
#define CPA_WAIT0()  asm volatile("cp.async.wait_group 0;" ::: "memory")
#define STG_H16(p, v) \
    asm volatile("st.global.cg.u16 [%0], %1;" :: "l"(p), "h"(v) : "memory")

static __device__ __forceinline__ void bar_arrive(unsigned* p) {
    asm volatile("red.release.gpu.global.add.u32 [%0], 1;" :: "l"(p) : "memory");
}
static __device__ __forceinline__ void bar_poll(unsigned* p, unsigned target) {
    unsigned cur;
    do {
        asm volatile("ld.acquire.gpu.global.u32 %0, [%1];"
                     : "=r"(cur) : "l"(p) : "memory");
    } while (cur < target);
}
static __device__ __forceinline__ unsigned ldcg_u32(const __half* p) {
    unsigned v;
    asm volatile("ld.global.cg.u32 %0, [%1];" : "=r"(v) : "l"(p) : "memory");
    return v;
}

// ---------------- prep: weight conversions ----------------
__global__ void prep_weights(const float* __restrict__ W0, const float* __restrict__ W1,
                             const float* __restrict__ R0, const float* __restrict__ R1) {
    if (blockIdx.x == 0 && threadIdx.x < 4) g_bars[threadIdx.x * 32] = 0u;
    if (blockIdx.x == 0 && threadIdx.x < 8) g_chunk[threadIdx.x * 32] = 0u;
    int i = blockIdx.x * blockDim.x + threadIdx.x;
    if (i < NC_ * U_) {
        int n = i >> 9, k = i & 511;
        float v0 = W0[(size_t)k * NC_ + n];
        __half h0 = __float2half(v0);
        g_wh0[i] = h0;
        g_wl0[i] = __float2half(v0 - __half2float(h0));
        g_wh1[i] = __float2half(W1[(size_t)k * NC_ + n]);
        g_r0[i]  = __float2half(R0[(size_t)k * NC_ + n]);
        g_r1[i]  = __float2half(R1[(size_t)k * NC_ + n]);
    }
}

__global__ void split_x(const float* __restrict__ src) {
    size_t n = (size_t)M_ * U_;
    for (size_t i = (size_t)blockIdx.x * blockDim.x + threadIdx.x; i < n;
         i += (size_t)gridDim.x * blockDim.x)
        g_a16[i] = __float2half(src[i]);
}

// ---------------- one 128x128 projection tile (2-pass fp16) ----------------
static __device__ __forceinline__ void gemm_tile(const __half* __restrict__ wh,
                                                 const __half* __restrict__ wl,
                                                 const float* __restrict__ biasv,
                                                 float* __restrict__ Cout,
                                                 int m0, int n0, char* sm, uint32_t sb) {
    float* bias_s = (float*)(sm + 61440);
    const int tid = threadIdx.x, lane = tid & 31, wid = tid >> 5;
    const int wm = wid >> 1, wn = wid & 1;

    if (tid < 128) bias_s[tid] = biasv[n0 + tid];

    const int lrow = tid >> 2, lch = tid & 3;
    auto load_tile = [&](int kt, int stage) {
#pragma unroll
        for (int i = 0; i < 2; i++) {
            int row = lrow + i * 64;
            size_t go = (size_t)row * U_ + kt * 32 + lch * 8;
            uint32_t so = sb + stage * 30720 + row * 80 + lch * 16;
            CPA16(so,         (const char*)g_a16 + 2 * ((size_t)m0 * U_ + go));
            CPA16(so + 10240, (const char*)wh    + 2 * ((size_t)n0 * U_ + go));
            CPA16(so + 20480, (const char*)wl    + 2 * ((size_t)n0 * U_ + go));
        }
        CPA_COMMIT();
    };

    float acc[2][8][4];
#pragma unroll
    for (int f = 0; f < 2; f++)
#pragma unroll
        for (int j = 0; j < 8; j++)
#pragma unroll
            for (int c = 0; c < 4; c++) acc[f][j][c] = 0.f;

    const uint32_t aoff = (uint32_t)((wm * 32 + (lane & 15)) * 80 + ((lane >> 4) * 8) * 2);
    const uint32_t boff = (uint32_t)((wn * 64 + (lane & 7) + ((lane >> 4) & 1) * 8) * 80
                                     + (((lane >> 3) & 1) * 8) * 2);

    load_tile(0, 0);
    CPA_WAIT0();
    __syncthreads();

    int buf = 0;
#pragma unroll 1
    for (int kt = 0; kt < 16; kt++) {
        if (kt < 15) load_tile(kt + 1, buf ^ 1);
        const uint32_t sbase = sb + buf * 30720;
#pragma unroll
        for (int ks = 0; ks < 2; ks++) {
            const uint32_t kb = (uint32_t)(ks * 32);
            uint32_t a[2][4], bh[4][4], bl[4][4];
            LDSM4(a[0], sbase + aoff + kb);
            LDSM4(a[1], sbase + aoff + kb + 16 * 80);
#pragma unroll
            for (int p = 0; p < 4; p++) {
                LDSM4(bh[p], sbase + 10240 + boff + kb + p * 16 * 80);
                LDSM4(bl[p], sbase + 20480 + boff + kb + p * 16 * 80);
            }
#pragma unroll
            for (int f = 0; f < 2; f++)
#pragma unroll
                for (int j = 0; j < 8; j++) {
                    uint32_t h0 = bh[j >> 1][(j & 1) * 2], h1 = bh[j >> 1][(j & 1) * 2 + 1];
                    uint32_t l0 = bl[j >> 1][(j & 1) * 2], l1 = bl[j >> 1][(j & 1) * 2 + 1];
                    MMA_F16(acc[f][j], a[f], h0, h1);
                    MMA_F16(acc[f][j], a[f], l0, l1);
                }
        }
        if (kt < 15) {
            CPA_WAIT0();
            __syncthreads();
            buf ^= 1;
        }
    }

#pragma unroll
    for (int f = 0; f < 2; f++) {
        const int r0 = m0 + wm * 32 + f * 16 + (lane >> 2);
#pragma unroll
        for (int j = 0; j < 8; j++) {
            const int cl = wn * 64 + j * 8 + (lane & 3) * 2;
            const int cg = n0 + cl;
            float2 o0 = make_float2(acc[f][j][0] + bias_s[cl], acc[f][j][1] + bias_s[cl + 1]);
            float2 o1 = make_float2(acc[f][j][2] + bias_s[cl], acc[f][j][3] + bias_s[cl + 1]);
            *(float2*)(Cout + (size_t)r0 * NC_ + cg)       = o0;
            *(float2*)(Cout + (size_t)(r0 + 8) * NC_ + cg) = o1;
        }
    }
}

// chunk-0 only: 64 m-tiles (one per batch) x 12 n-tiles
__global__ __launch_bounds__(256) void gemm_mma(const float* __restrict__ bias) {
    extern __shared__ char smg[];
    gemm_tile(g_wh0, g_wl0, bias, g_xp, blockIdx.y * 8 * 128, blockIdx.x * 128,
              smg, smem_u32(smg));
}

// ---------------- split-SM wavefront + projection chasers ----------------
// CTAs 0..63: layer 0. CTAs 64..127: layer 1 (split-phase polls). CTAs 128..147:
// chasers producing g_xp t-chunks 1..7, gated by per-chunk counters.
__global__ __launch_bounds__(256, 1) void wave_rec(const float* __restrict__ b0v,
                                                   const float* __restrict__ b1v,
                                                   float* __restrict__ out1,
                                                   float* __restrict__ hl0,
                                                   float* __restrict__ hl1) {
    extern __shared__ char smb[];
    float* red = (float*)smb;
    const int tid = threadIdx.x, lane = tid & 31, w = tid >> 5;
    const int bid = blockIdx.x;

    if (bid >= 128) {
        // ---- chasers: produce chunks 1..7 of layer-0 projections ----
        const uint32_t sb = smem_u32(smb);
        const int cid = bid - 128;
        for (int tt = cid; tt < 7 * 768; tt += 20) {
            int c = 1 + tt / 768;
            int i = tt % 768;
            int b = i / 12, nn = i % 12;
            __syncthreads();
            gemm_tile(g_wh0, g_wl0, b0v, g_xp, (b * 8 + c) * 128, nn * 128, smb, sb);
            __syncthreads();
            if (tid == 0) bar_arrive(&g_chunk[c * 32]);
        }
        return;
    }

    const bool isL1 = bid >= 64;
    const int lb = isL1 ? bid - 64 : bid;
    const int bg = lb >> 5, ug = lb & 31;
    const int b_base = bg * 32, u_base = ug * 16;
    unsigned* c0 = &g_bars[(bg * 2 + 0) * 32];
    unsigned* c1 = &g_bars[(bg * 2 + 1) * 32];

    const int nl = lane >> 2, kq = (lane & 3) * 2;
    const int m = lane >> 2, n0r = (lane & 3) * 2;
    const int r0 = lane >> 2, cb = (lane & 3) * 2;
    const int b_loc = tid >> 3;
    const int u0 = (tid & 7) * 2;
    const int b_glob = b_base + b_loc;

    if (!isL1) {
        // ================= LAYER 0 =================
        const int kbase = w * 64;
        uint32_t rb[6][4][2];
#pragma unroll
        for (int nt = 0; nt < 6; nt++) {
            int ncol = nt * 8 + nl;
            int g = ncol >> 4, ul = ncol & 15;
            const __half* rp = g_r0 + ((size_t)(g * 512 + u_base + ul)) * 512;
#pragma unroll
            for (int ks = 0; ks < 4; ks++) {
                int k0 = kbase + ks * 16 + kq;
                rb[nt][ks][0] = *(const uint32_t*)(rp + k0);
                rb[nt][ks][1] = *(const uint32_t*)(rp + k0 + 8);
            }
        }

        float bz[2], brr[2], bhhc[2], hown[2];
        const float* xpp = g_xp + (size_t)b_glob * T_ * NC_;
#pragma unroll
        for (int j = 0; j < 2; j++) {
            int ugl = u_base + u0 + j;
            bz[j]   = b0v[NC_ + ugl];
            brr[j]  = b0v[NC_ + U_ + ugl];
            bhhc[j] = b0v[NC_ + 2 * U_ + ugl];
            hown[j] = 0.0f;
        }
        const int cc = kbase + cb;

        int pw = 0, pr = 2;
        for (int s = 0; s < T_; s++) {
            // polls: own group at s; L1 lag (buffer free); xp chunk produced
            if (s >= 1) {
                bar_poll(c0, 32u * (unsigned)s);
                if (s >= 3) bar_poll(c1, 32u * (unsigned)(s - 2));
            }
            if (s >= 128 && (s & 127) == 0) bar_poll(&g_chunk[(s >> 7) * 32], 768u);

            // x loads for THIS step (row s guaranteed produced)
            float xz[2], xr[2], xh[2];
#pragma unroll
            for (int j = 0; j < 2; j++) {
                int ugl = u_base + u0 + j;
                const float* xrow = xpp + (size_t)s * NC_;
                xz[j] = __ldg(xrow + ugl);
                xr[j] = __ldg(xrow + U_ + ugl);
                xh[j] = __ldg(xrow + 2 * U_ + ugl);
            }

            uint32_t af[2][4][4];
            if (s == 0) {
#pragma unroll
                for (int mt = 0; mt < 2; mt++)
#pragma unroll
                    for (int ks = 0; ks < 4; ks++)
#pragma unroll
                        for (int c = 0; c < 4; c++) af[mt][ks][c] = 0u;
            } else {
                const __half* hg = g_hx0[pr] + (size_t)b_base * U_;
#pragma unroll
                for (int mt = 0; mt < 2; mt++)
#pragma unroll
                    for (int ks = 0; ks < 4; ks++) {
                        const __half* hp = hg + (size_t)(mt * 16 + r0) * U_ + cc + ks * 16;
                        af[mt][ks][0] = ldcg_u32(hp);
                        af[mt][ks][1] = ldcg_u32(hp + 8 * U_);
                        af[mt][ks][2] = ldcg_u32(hp + 8);
                        af[mt][ks][3] = ldcg_u32(hp + 8 * U_ + 8);
                    }
            }

            float acc[2][6][4];
#pragma unroll
            for (int mt = 0; mt < 2; mt++)
#pragma unroll
                for (int nt = 0; nt < 6; nt++)
#pragma unroll
                    for (int c = 0; c < 4; c++) acc[mt][nt][c] = 0.f;
#pragma unroll
            for (int ks = 0; ks < 4; ks++)
#pragma unroll
                for (int nt = 0; nt < 6; nt++) {
                    MMA_F16(acc[0][nt], af[0][ks], rb[nt][ks][0], rb[nt][ks][1]);
                    MMA_F16(acc[1][nt], af[1][ks], rb[nt][ks][0], rb[nt][ks][1]);
                }
#pragma unroll
            for (int mt = 0; mt < 2; mt++)
#pragma unroll
                for (int nt = 0; nt < 6; nt++) {
                    float* r0p = red + (size_t)(w * 32 + mt * 16 + m) * 50 + nt * 8 + n0r;
                    *(float2*)r0p = make_float2(acc[mt][nt][0], acc[mt][nt][1]);
                    *(float2*)(r0p + 8 * 50) = make_float2(acc[mt][nt][2], acc[mt][nt][3]);
                }
            __syncthreads();

#pragma unroll
            for (int j = 0; j < 2; j++) {
                int u_loc = u0 + j;
                float s0 = 0.f, s1 = 0.f, s2 = 0.f;
#pragma unroll
                for (int ww = 0; ww < 8; ww++) {
                    const float* rr = red + (size_t)(ww * 32 + b_loc) * 50;
                    s0 += rr[u_loc];
                    s1 += rr[16 + u_loc];
                    s2 += rr[32 + u_loc];
                }
                float z  = fsig(xz[j] + s0 + bz[j]);
                float r  = fsig(xr[j] + s1 + brr[j]);
                float hh = ftanh(xh[j] + r * (s2 + bhhc[j]));
                float hn = z * hown[j] + (1.0f - z) * hh;
                hown[j] = hn;
                STG_H16(&g_hx0[pw][(size_t)b_glob * U_ + u_base + u_loc],
                        __half_as_ushort(__float2half(hn)));
                if (s == T_ - 1) hl0[(size_t)b_glob * U_ + u_base + u_loc] = hn;
            }
            __syncthreads();
            if (tid == 0) bar_arrive(c0);
            pr = pw;
            pw = (pw == 2) ? 0 : pw + 1;
        }
    } else {
        // ================= LAYER 1 (split-phase polls) =================
        const int kbaseA = w * 128;
        const __half* WZ = (w < 4) ? g_wh1 : g_r1;
        const int kW = (w < 4) ? kbaseA : kbaseA - 512;

        uint32_t rzr[4][8][2];
#pragma unroll
        for (int nt = 0; nt < 4; nt++) {
            int ncol = nt * 8 + nl;
            int g = ncol >> 4, ul = ncol & 15;
            const __half* rp = WZ + ((size_t)(g * 512 + u_base + ul)) * 512;
#pragma unroll
            for (int ks = 0; ks < 8; ks++) {
                int k0 = kW + ks * 16 + kq;
                rzr[nt][ks][0] = *(const uint32_t*)(rp + k0);
                rzr[nt][ks][1] = *(const uint32_t*)(rp + k0 + 8);
            }
        }
        uint32_t rhh[2][8][2];
#pragma unroll
        for (int nt = 0; nt < 2; nt++) {
            int ul = nt * 8 + nl;
            const __half* rp = WZ + ((size_t)(1024 + u_base + ul)) * 512;
#pragma unroll
            for (int ks = 0; ks < 8; ks++) {
                int k0 = kW + ks * 16 + kq;
                rhh[nt][ks][0] = *(const uint32_t*)(rp + k0);
                rhh[nt][ks][1] = *(const uint32_t*)(rp + k0 + 8);
            }
        }

        float cz[2], cr[2], bih[2], bhh2[2], hown[2];
#pragma unroll
        for (int j = 0; j < 2; j++) {
            int ugl = u_base + u0 + j;
            cz[j]   = b1v[ugl] + b1v[NC_ + ugl];
            cr[j]   = b1v[U_ + ugl] + b1v[NC_ + U_ + ugl];
            bih[j]  = b1v[2 * U_ + ugl];
            bhh2[j] = b1v[NC_ + 2 * U_ + ugl];
            hown[j] = 0.0f;
        }
        const int cc = kW + cb;

        int ph = 0;
        for (int s = 1; s <= T_; s++) {
            // SPLIT-PHASE polls: only the counter this warp's data needs.
            if (w < 4) {
                bar_poll(c0, 32u * (unsigned)s);          // y0_{s-1} ready
            } else {
                if (s >= 2) bar_poll(c1, 32u * (unsigned)(s - 1));  // h1_{s-2} + own lag
            }

            const __half* asrc = ((w < 4) ? g_hx0[ph] : g_hx1[s & 1])
                                 + (size_t)b_base * U_;
            const bool azero = (w >= 4 && s == 1);

            float acc[2][6][4];
#pragma unroll
            for (int mt = 0; mt < 2; mt++)
#pragma unroll
                for (int nt = 0; nt < 6; nt++)
#pragma unroll
                    for (int c = 0; c < 4; c++) acc[mt][nt][c] = 0.f;

#pragma unroll
            for (int half = 0; half < 2; half++) {
                uint32_t af[2][4][4];
#pragma unroll
                for (int mt = 0; mt < 2; mt++)
#pragma unroll
                    for (int kk = 0; kk < 4; kk++) {
                        int ks = half * 4 + kk;
                        if (azero) {
                            af[mt][kk][0] = af[mt][kk][1] = 0u;
                            af[mt][kk][2] = af[mt][kk][3] = 0u;
                        } else {
                            const __half* hp = asrc + (size_t)(mt * 16 + r0) * U_ + cc + ks * 16;
                            af[mt][kk][0] = ldcg_u32(hp);
                            af[mt][kk][1] = ldcg_u32(hp + 8 * U_);
                            af[mt][kk][2] = ldcg_u32(hp + 8);
                            af[mt][kk][3] = ldcg_u32(hp + 8 * U_ + 8);
                        }
                    }
#pragma unroll
                for (int kk = 0; kk < 4; kk++) {
                    int ks = half * 4 + kk;
#pragma unroll
                    for (int nt = 0; nt < 4; nt++) {
                        MMA_F16(acc[0][nt], af[0][kk], rzr[nt][ks][0], rzr[nt][ks][1]);
                        MMA_F16(acc[1][nt], af[1][kk], rzr[nt][ks][0], rzr[nt][ks][1]);
                    }
#pragma unroll
                    for (int nt = 0; nt < 2; nt++) {
                        MMA_F16(acc[0][4 + nt], af[0][kk], rhh[nt][ks][0], rhh[nt][ks][1]);
                        MMA_F16(acc[1][4 + nt], af[1][kk], rhh[nt][ks][0], rhh[nt][ks][1]);
                    }
                }
            }

#pragma unroll
            for (int mt = 0; mt < 2; mt++) {
#pragma unroll
                for (int nt = 0; nt < 4; nt++) {
                    float* r0p = red + (size_t)(w * 32 + mt * 16 + m) * 52 + nt * 8 + n0r;
                    *(float2*)r0p = make_float2(acc[mt][nt][0], acc[mt][nt][1]);
                    *(float2*)(r0p + 8 * 52) = make_float2(acc[mt][nt][2], acc[mt][nt][3]);
                }
#pragma unroll
                for (int nt = 0; nt < 2; nt++) {
                    float* r0p = red + (size_t)(w * 32 + mt * 16 + m) * 52 + 32 + nt * 8 + n0r;
                    *(float2*)r0p = make_float2(acc[mt][4 + nt][0], acc[mt][4 + nt][1]);
                    *(float2*)(r0p + 8 * 52) = make_float2(acc[mt][4 + nt][2], acc[mt][4 + nt][3]);
                }
            }
            __syncthreads();

#pragma unroll
            for (int j = 0; j < 2; j++) {
                int u_loc = u0 + j;
                float zv = 0.f, rv = 0.f, pv = 0.f, qv = 0.f;
#pragma unroll
                for (int ww = 0; ww < 8; ww++) {
                    const float* rr = red + (size_t)(ww * 32 + b_loc) * 52;
                    zv += rr[u_loc];
                    rv += rr[16 + u_loc];
                    if (ww < 4) pv += rr[32 + u_loc];
                    else        qv += rr[32 + u_loc];
                }
                float z  = fsig(zv + cz[j]);
                float r  = fsig(rv + cr[j]);
                float hh = ftanh(pv + bih[j] + r * (qv + bhh2[j]));
                float hn = z * hown[j] + (1.0f - z) * hh;
                hown[j] = hn;
                out1[(size_t)b_glob * T_ * U_ + (size_t)(s - 1) * U_ + u_base + u_loc] = hn;
                if (s <= T_ - 1)
                    STG_H16(&g_hx1[(s - 1) & 1][(size_t)b_glob * U_ + u_base + u_loc],
                            __half_as_ushort(__float2half(hn)));
                if (s == T_) hl1[(size_t)b_glob * U_ + u_base + u_loc] = hn;
            }
            __syncthreads();
            if (tid == 0) bar_arrive(c1);
            ph = (ph == 2) ? 0 : ph + 1;
        }
    }
}

// ---------------- launcher ----------------
extern "C" void kernel_launch(void* const* d_in, const int* in_sizes, int n_in,
                              void* d_out, int out_size) {
    const float* x  = (const float*)d_in[0];
    const float* W0 = (const float*)d_in[1];
    const float* R0 = (const float*)d_in[2];
    const float* b0 = (const float*)d_in[3];
    const float* W1 = (const float*)d_in[4];
    const float* R1 = (const float*)d_in[5];
    const float* b1 = (const float*)d_in[6];

    float* out  = (float*)d_out;
    float* out1 = out;                               // [64,1024,512]
    float* h0   = out + (size_t)B_ * T_ * U_;        // [64,512]
    float* h1   = h0 + (size_t)B_ * U_;              // [64,512]

    cudaFuncSetAttribute(wave_rec, cudaFuncAttributeMaxDynamicSharedMemorySize,
                         SMEM_WAVE);
    cudaFuncSetAttribute(gemm_mma, cudaFuncAttributeMaxDynamicSharedMemorySize,
                         SMEM_GEMM);

    prep_weights<<<NC_ * U_ / 256, 256>>>(W0, W1, R0, R1);       // 0
    split_x<<<4096, 256>>>(x);                                   // 1
    dim3 gc0(12, 64);
    gemm_mma<<<gc0, 256, SMEM_GEMM>>>(b0);                       // 2: chunk 0 only
    wave_rec<<<148, 256, SMEM_WAVE>>>(b0, b1, out1, h0, h1);     // 3 -> ncu
}

// round 17
// speedup vs baseline: 1.5463x; 1.0221x over previous
#include <cuda_runtime.h>
#include <cuda_fp16.h>
#include <cstdint>

#define B_  64
#define T_  1024
#define U_  512
#define NC_ 1536
#define M_  (B_ * T_)          // 65536
#define SMEM_WAVE 121856       // forces 1 CTA/SM for the persistent grid
#define SMEM_GEMM 61952

// ---------------- device scratch ----------------
__device__ float    g_xp [(size_t)M_ * NC_];      // layer-0 input projections
__device__ unsigned g_bars[4 * 32];               // [bg*2+layer] counters, 128B apart
__device__ unsigned g_chunk[8 * 32];              // per-t-chunk production counters
__device__ __half   g_a16[(size_t)M_ * U_];       // x (fp16) [m][k]
__device__ __half   g_wh0[(size_t)NC_ * U_];      // W0^T hi [n][k]
__device__ __half   g_wl0[(size_t)NC_ * U_];      // W0^T lo
__device__ __half   g_wh1[(size_t)NC_ * U_];      // W1^T fp16 [n][k]
__device__ __half   g_r0 [(size_t)NC_ * U_];      // R0^T fp16 [n][k]
__device__ __half   g_r1 [(size_t)NC_ * U_];      // R1^T fp16
// h exchange in mma A-FRAGMENT layout: [par][b16][ktile(32)][lane(32)][reg(4)] u32
__device__ unsigned g_hx0f[3][4 * 32 * 32 * 4];   // h0, triple buffered
__device__ unsigned g_hx1f[2][4 * 32 * 32 * 4];   // h1, double buffered

// ---------------- helpers ----------------
static __device__ __forceinline__ float fsig(float x) {
    return __fdividef(1.0f, 1.0f + __expf(-x));
}
static __device__ __forceinline__ float ftanh(float x) {
    return 1.0f - __fdividef(2.0f, __expf(2.0f * x) + 1.0f);
}
static __device__ __forceinline__ uint32_t smem_u32(const void* p) {
    uint32_t a;
    asm("{ .reg .u64 t; cvta.to.shared.u64 t, %1; cvt.u32.u64 %0, t; }"
        : "=r"(a) : "l"(p));
    return a;
}
#define LDSM4(r, addr) \
    asm volatile("ldmatrix.sync.aligned.m8n8.x4.shared.b16 {%0,%1,%2,%3}, [%4];" \
        : "=r"((r)[0]), "=r"((r)[1]), "=r"((r)[2]), "=r"((r)[3]) : "r"(addr))
#define MMA_F16(d, a, b0v, b1v) \
    asm volatile("mma.sync.aligned.m16n8k16.row.col.f32.f16.f16.f32 " \
        "{%0,%1,%2,%3}, {%4,%5,%6,%7}, {%8,%9}, {%0,%1,%2,%3};" \
        : "+f"((d)[0]), "+f"((d)[1]), "+f"((d)[2]), "+f"((d)[3]) \
        : "r"((a)[0]), "r"((a)[1]), "r"((a)[2]), "r"((a)[3]), "r"(b0v), "r"(b1v))
#define CPA16(dst, src) \
    asm volatile("cp.async.cg.shared.global [%0], [%1], 16;" :: "r"(dst), "l"(src))
#define CPA_COMMIT() asm volatile("cp.async.commit_group;")
#define CPA_WAIT0()  asm volatile("cp.async.wait_group 0;" ::: "memory")
#define STG_U32(p, v) \
    asm volatile("st.global.cg.u32 [%0], %1;" :: "l"(p), "r"(v) : "memory")

static __device__ __forceinline__ void bar_arrive(unsigned* p) {
    asm volatile("red.release.gpu.global.add.u32 [%0], 1;" :: "l"(p) : "memory");
}
static __device__ __forceinline__ void bar_poll(unsigned* p, unsigned target) {
    unsigned cur;
    do {
        asm volatile("ld.acquire.gpu.global.u32 %0, [%1];"
                     : "=r"(cur) : "l"(p) : "memory");
    } while (cur < target);
}
static __device__ __forceinline__ uint4 ldcg_v4(const unsigned* p) {
    uint4 v;
    asm volatile("ld.global.cg.v4.u32 {%0,%1,%2,%3}, [%4];"
                 : "=r"(v.x), "=r"(v.y), "=r"(v.z), "=r"(v.w) : "l"(p) : "memory");
    return v;
}

// ---------------- prep: weight conversions ----------------
__global__ void prep_weights(const float* __restrict__ W0, const float* __restrict__ W1,
                             const float* __restrict__ R0, const float* __restrict__ R1) {
    if (blockIdx.x == 0 && threadIdx.x < 4) g_bars[threadIdx.x * 32] = 0u;
    if (blockIdx.x == 0 && threadIdx.x < 8) g_chunk[threadIdx.x * 32] = 0u;
    int i = blockIdx.x * blockDim.x + threadIdx.x;
    if (i < NC_ * U_) {
        int n = i >> 9, k = i & 511;
        float v0 = W0[(size_t)k * NC_ + n];
        __half h0 = __float2half(v0);
        g_wh0[i] = h0;
        g_wl0[i] = __float2half(v0 - __half2float(h0));
        g_wh1[i] = __float2half(W1[(size_t)k * NC_ + n]);
        g_r0[i]  = __float2half(R0[(size_t)k * NC_ + n]);
        g_r1[i]  = __float2half(R1[(size_t)k * NC_ + n]);
    }
}

__global__ void split_x(const float* __restrict__ src) {
    size_t n = (size_t)M_ * U_;
    for (size_t i = (size_t)blockIdx.x * blockDim.x + threadIdx.x; i < n;
         i += (size_t)gridDim.x * blockDim.x)
        g_a16[i] = __float2half(src[i]);
}

// ---------------- one 128x128 projection tile (2-pass fp16) ----------------
static __device__ __forceinline__ void gemm_tile(const __half* __restrict__ wh,
                                                 const __half* __restrict__ wl,
                                                 const float* __restrict__ biasv,
                                                 float* __restrict__ Cout,
                                                 int m0, int n0, char* sm, uint32_t sb) {
    float* bias_s = (float*)(sm + 61440);
    const int tid = threadIdx.x, lane = tid & 31, wid = tid >> 5;
    const int wm = wid >> 1, wn = wid & 1;

    if (tid < 128) bias_s[tid] = biasv[n0 + tid];

    const int lrow = tid >> 2, lch = tid & 3;
    auto load_tile = [&](int kt, int stage) {
#pragma unroll
        for (int i = 0; i < 2; i++) {
            int row = lrow + i * 64;
            size_t go = (size_t)row * U_ + kt * 32 + lch * 8;
            uint32_t so = sb + stage * 30720 + row * 80 + lch * 16;
            CPA16(so,         (const char*)g_a16 + 2 * ((size_t)m0 * U_ + go));
            CPA16(so + 10240, (const char*)wh    + 2 * ((size_t)n0 * U_ + go));
            CPA16(so + 20480, (const char*)wl    + 2 * ((size_t)n0 * U_ + go));
        }
        CPA_COMMIT();
    };

    float acc[2][8][4];
#pragma unroll
    for (int f = 0; f < 2; f++)
#pragma unroll
        for (int j = 0; j < 8; j++)
#pragma unroll
            for (int c = 0; c < 4; c++) acc[f][j][c] = 0.f;

    const uint32_t aoff = (uint32_t)((wm * 32 + (lane & 15)) * 80 + ((lane >> 4) * 8) * 2);
    const uint32_t boff = (uint32_t)((wn * 64 + (lane & 7) + ((lane >> 4) & 1) * 8) * 80
                                     + (((lane >> 3) & 1) * 8) * 2);

    load_tile(0, 0);
    CPA_WAIT0();
    __syncthreads();

    int buf = 0;
#pragma unroll 1
    for (int kt = 0; kt < 16; kt++) {
        if (kt < 15) load_tile(kt + 1, buf ^ 1);
        const uint32_t sbase = sb + buf * 30720;
#pragma unroll
        for (int ks = 0; ks < 2; ks++) {
            const uint32_t kb = (uint32_t)(ks * 32);
            uint32_t a[2][4], bh[4][4], bl[4][4];
            LDSM4(a[0], sbase + aoff + kb);
            LDSM4(a[1], sbase + aoff + kb + 16 * 80);
#pragma unroll
            for (int p = 0; p < 4; p++) {
                LDSM4(bh[p], sbase + 10240 + boff + kb + p * 16 * 80);
                LDSM4(bl[p], sbase + 20480 + boff + kb + p * 16 * 80);
            }
#pragma unroll
            for (int f = 0; f < 2; f++)
#pragma unroll
                for (int j = 0; j < 8; j++) {
                    uint32_t h0 = bh[j >> 1][(j & 1) * 2], h1 = bh[j >> 1][(j & 1) * 2 + 1];
                    uint32_t l0 = bl[j >> 1][(j & 1) * 2], l1 = bl[j >> 1][(j & 1) * 2 + 1];
                    MMA_F16(acc[f][j], a[f], h0, h1);
                    MMA_F16(acc[f][j], a[f], l0, l1);
                }
        }
        if (kt < 15) {
            CPA_WAIT0();
            __syncthreads();
            buf ^= 1;
        }
    }

#pragma unroll
    for (int f = 0; f < 2; f++) {
        const int r0 = m0 + wm * 32 + f * 16 + (lane >> 2);
#pragma unroll
        for (int j = 0; j < 8; j++) {
            const int cl = wn * 64 + j * 8 + (lane & 3) * 2;
            const int cg = n0 + cl;
            float2 o0 = make_float2(acc[f][j][0] + bias_s[cl], acc[f][j][1] + bias_s[cl + 1]);
            float2 o1 = make_float2(acc[f][j][2] + bias_s[cl], acc[f][j][3] + bias_s[cl + 1]);
            *(float2*)(Cout + (size_t)r0 * NC_ + cg)       = o0;
            *(float2*)(Cout + (size_t)(r0 + 8) * NC_ + cg) = o1;
        }
    }
}

// chunk-0 only: 64 m-tiles (one per batch) x 12 n-tiles
__global__ __launch_bounds__(256) void gemm_mma(const float* __restrict__ bias) {
    extern __shared__ char smg[];
    gemm_tile(g_wh0, g_wl0, bias, g_xp, blockIdx.y * 8 * 128, blockIdx.x * 128,
              smg, smem_u32(smg));
}

// ---------------- split-SM wavefront + projection chasers ----------------
__global__ __launch_bounds__(256, 1) void wave_rec(const float* __restrict__ b0v,
                                                   const float* __restrict__ b1v,
                                                   float* __restrict__ out1,
                                                   float* __restrict__ hl0,
                                                   float* __restrict__ hl1) {
    extern __shared__ char smb[];
    float* red = (float*)smb;
    const int tid = threadIdx.x, lane = tid & 31, w = tid >> 5;
    const int bid = blockIdx.x;

    if (bid >= 128) {
        // ---- chasers: produce chunks 1..7 of layer-0 projections ----
        const uint32_t sb = smem_u32(smb);
        const int cid = bid - 128;
        for (int tt = cid; tt < 7 * 768; tt += 20) {
            int c = 1 + tt / 768;
            int i = tt % 768;
            int b = i / 12, nn = i % 12;
            __syncthreads();
            gemm_tile(g_wh0, g_wl0, b0v, g_xp, (b * 8 + c) * 128, nn * 128, smb, sb);
            __syncthreads();
            if (tid == 0) bar_arrive(&g_chunk[c * 32]);
        }
        return;
    }

    const bool isL1 = bid >= 64;
    const int lb = isL1 ? bid - 64 : bid;
    const int bg = lb >> 5, ug = lb & 31;
    const int b_base = bg * 32, u_base = ug * 16;
    unsigned* c0 = &g_bars[(bg * 2 + 0) * 32];
    unsigned* c1 = &g_bars[(bg * 2 + 1) * 32];

    const int nl = lane >> 2, kq = (lane & 3) * 2;
    const int m = lane >> 2, n0r = (lane & 3) * 2;
    const int b_loc = tid >> 3;
    const int u0 = (tid & 7) * 2;
    const int b_glob = b_base + b_loc;

    // fragment-layout write offset for owner thread (units u_base+u0, +1 of batch b_glob)
    const int fb16 = b_glob >> 4;
    const int fr = b_glob & 15;
    const int flane = (fr & 7) * 4 + ((u0 & 7) >> 1);
    const int freg = (fr >> 3) + 2 * (u0 >> 3);
    const int fwoff = ((fb16 * 32 + ug) * 32 + flane) * 4 + freg;

    if (!isL1) {
        // ================= LAYER 0 =================
        const int kbase = w * 64;
        uint32_t rb[6][4][2];
#pragma unroll
        for (int nt = 0; nt < 6; nt++) {
            int ncol = nt * 8 + nl;
            int g = ncol >> 4, ul = ncol & 15;
            const __half* rp = g_r0 + ((size_t)(g * 512 + u_base + ul)) * 512;
#pragma unroll
            for (int ks = 0; ks < 4; ks++) {
                int k0 = kbase + ks * 16 + kq;
                rb[nt][ks][0] = *(const uint32_t*)(rp + k0);
                rb[nt][ks][1] = *(const uint32_t*)(rp + k0 + 8);
            }
        }

        float bz[2], brr[2], bhhc[2], hown[2];
        const float* xpp = g_xp + (size_t)b_glob * T_ * NC_;
#pragma unroll
        for (int j = 0; j < 2; j++) {
            int ugl = u_base + u0 + j;
            bz[j]   = b0v[NC_ + ugl];
            brr[j]  = b0v[NC_ + U_ + ugl];
            bhhc[j] = b0v[NC_ + 2 * U_ + ugl];
            hown[j] = 0.0f;
        }

        int pw = 0, pr = 2;
        for (int s = 0; s < T_; s++) {
            if (s >= 1) {
                bar_poll(c0, 32u * (unsigned)s);
                if (s >= 3) bar_poll(c1, 32u * (unsigned)(s - 2));
            }
            if (s >= 128 && (s & 127) == 0) bar_poll(&g_chunk[(s >> 7) * 32], 768u);

            float xz[2], xr[2], xh[2];
#pragma unroll
            for (int j = 0; j < 2; j++) {
                int ugl = u_base + u0 + j;
                const float* xrow = xpp + (size_t)s * NC_;
                xz[j] = __ldg(xrow + ugl);
                xr[j] = __ldg(xrow + U_ + ugl);
                xh[j] = __ldg(xrow + 2 * U_ + ugl);
            }

            // A fragments: one LDG.128 per (mt, ks)
            uint32_t af[2][4][4];
            if (s == 0) {
#pragma unroll
                for (int mt = 0; mt < 2; mt++)
#pragma unroll
                    for (int ks = 0; ks < 4; ks++)
#pragma unroll
                        for (int c = 0; c < 4; c++) af[mt][ks][c] = 0u;
            } else {
                const unsigned* hg = g_hx0f[pr];
#pragma unroll
                for (int mt = 0; mt < 2; mt++)
#pragma unroll
                    for (int ks = 0; ks < 4; ks++) {
                        uint4 v = ldcg_v4(hg + (((bg * 2 + mt) * 32 + (w * 4 + ks)) * 32 + lane) * 4);
                        af[mt][ks][0] = v.x; af[mt][ks][1] = v.y;
                        af[mt][ks][2] = v.z; af[mt][ks][3] = v.w;
                    }
            }

            float acc[2][6][4];
#pragma unroll
            for (int mt = 0; mt < 2; mt++)
#pragma unroll
                for (int nt = 0; nt < 6; nt++)
#pragma unroll
                    for (int c = 0; c < 4; c++) acc[mt][nt][c] = 0.f;
#pragma unroll
            for (int ks = 0; ks < 4; ks++)
#pragma unroll
                for (int nt = 0; nt < 6; nt++) {
                    MMA_F16(acc[0][nt], af[0][ks], rb[nt][ks][0], rb[nt][ks][1]);
                    MMA_F16(acc[1][nt], af[1][ks], rb[nt][ks][0], rb[nt][ks][1]);
                }
#pragma unroll
            for (int mt = 0; mt < 2; mt++)
#pragma unroll
                for (int nt = 0; nt < 6; nt++) {
                    float* r0p = red + (size_t)(w * 32 + mt * 16 + m) * 50 + nt * 8 + n0r;
                    *(float2*)r0p = make_float2(acc[mt][nt][0], acc[mt][nt][1]);
                    *(float2*)(r0p + 8 * 50) = make_float2(acc[mt][nt][2], acc[mt][nt][3]);
                }
            __syncthreads();

            float hn2[2];
#pragma unroll
            for (int j = 0; j < 2; j++) {
                int u_loc = u0 + j;
                float s0 = 0.f, s1 = 0.f, s2 = 0.f;
#pragma unroll
                for (int ww = 0; ww < 8; ww++) {
                    const float* rr = red + (size_t)(ww * 32 + b_loc) * 50;
                    s0 += rr[u_loc];
                    s1 += rr[16 + u_loc];
                    s2 += rr[32 + u_loc];
                }
                float z  = fsig(xz[j] + s0 + bz[j]);
                float r  = fsig(xr[j] + s1 + brr[j]);
                float hh = ftanh(xh[j] + r * (s2 + bhhc[j]));
                float hn = z * hown[j] + (1.0f - z) * hh;
                hown[j] = hn;
                hn2[j] = hn;
                if (s == T_ - 1) hl0[(size_t)b_glob * U_ + u_base + u_loc] = hn;
            }
            unsigned pv = (unsigned)__half_as_ushort(__float2half(hn2[0])) |
                          ((unsigned)__half_as_ushort(__float2half(hn2[1])) << 16);
            STG_U32(&g_hx0f[pw][fwoff], pv);
            __syncthreads();
            if (tid == 0) bar_arrive(c0);
            pr = pw;
            pw = (pw == 2) ? 0 : pw + 1;
        }
    } else {
        // ================= LAYER 1 (split-phase polls) =================
        const int kbaseA = w * 128;
        const __half* WZ = (w < 4) ? g_wh1 : g_r1;
        const int kW = (w < 4) ? kbaseA : kbaseA - 512;

        uint32_t rzr[4][8][2];
#pragma unroll
        for (int nt = 0; nt < 4; nt++) {
            int ncol = nt * 8 + nl;
            int g = ncol >> 4, ul = ncol & 15;
            const __half* rp = WZ + ((size_t)(g * 512 + u_base + ul)) * 512;
#pragma unroll
            for (int ks = 0; ks < 8; ks++) {
                int k0 = kW + ks * 16 + kq;
                rzr[nt][ks][0] = *(const uint32_t*)(rp + k0);
                rzr[nt][ks][1] = *(const uint32_t*)(rp + k0 + 8);
            }
        }
        uint32_t rhh[2][8][2];
#pragma unroll
        for (int nt = 0; nt < 2; nt++) {
            int ul = nt * 8 + nl;
            const __half* rp = WZ + ((size_t)(1024 + u_base + ul)) * 512;
#pragma unroll
            for (int ks = 0; ks < 8; ks++) {
                int k0 = kW + ks * 16 + kq;
                rhh[nt][ks][0] = *(const uint32_t*)(rp + k0);
                rhh[nt][ks][1] = *(const uint32_t*)(rp + k0 + 8);
            }
        }

        float cz[2], cr[2], bih[2], bhh2[2], hown[2];
#pragma unroll
        for (int j = 0; j < 2; j++) {
            int ugl = u_base + u0 + j;
            cz[j]   = b1v[ugl] + b1v[NC_ + ugl];
            cr[j]   = b1v[U_ + ugl] + b1v[NC_ + U_ + ugl];
            bih[j]  = b1v[2 * U_ + ugl];
            bhh2[j] = b1v[NC_ + 2 * U_ + ugl];
            hown[j] = 0.0f;
        }
        const int ktb = (w < 4) ? w * 8 : (w - 4) * 8;   // fragment k-tile base

        int ph = 0;
        for (int s = 1; s <= T_; s++) {
            if (w < 4) {
                bar_poll(c0, 32u * (unsigned)s);
            } else {
                if (s >= 2) bar_poll(c1, 32u * (unsigned)(s - 1));
            }

            const unsigned* asrc = (w < 4) ? g_hx0f[ph] : g_hx1f[s & 1];
            const bool azero = (w >= 4 && s == 1);

            float acc[2][6][4];
#pragma unroll
            for (int mt = 0; mt < 2; mt++)
#pragma unroll
                for (int nt = 0; nt < 6; nt++)
#pragma unroll
                    for (int c = 0; c < 4; c++) acc[mt][nt][c] = 0.f;

#pragma unroll
            for (int half = 0; half < 2; half++) {
                uint32_t af[2][4][4];
#pragma unroll
                for (int mt = 0; mt < 2; mt++)
#pragma unroll
                    for (int kk = 0; kk < 4; kk++) {
                        if (azero) {
                            af[mt][kk][0] = af[mt][kk][1] = 0u;
                            af[mt][kk][2] = af[mt][kk][3] = 0u;
                        } else {
                            int ktile = ktb + half * 4 + kk;
                            uint4 v = ldcg_v4(asrc +
                                (((bg * 2 + mt) * 32 + ktile) * 32 + lane) * 4);
                            af[mt][kk][0] = v.x; af[mt][kk][1] = v.y;
                            af[mt][kk][2] = v.z; af[mt][kk][3] = v.w;
                        }
                    }
#pragma unroll
                for (int kk = 0; kk < 4; kk++) {
                    int ks = half * 4 + kk;
#pragma unroll
                    for (int nt = 0; nt < 4; nt++) {
                        MMA_F16(acc[0][nt], af[0][kk], rzr[nt][ks][0], rzr[nt][ks][1]);
                        MMA_F16(acc[1][nt], af[1][kk], rzr[nt][ks][0], rzr[nt][ks][1]);
                    }
#pragma unroll
                    for (int nt = 0; nt < 2; nt++) {
                        MMA_F16(acc[0][4 + nt], af[0][kk], rhh[nt][ks][0], rhh[nt][ks][1]);
                        MMA_F16(acc[1][4 + nt], af[1][kk], rhh[nt][ks][0], rhh[nt][ks][1]);
                    }
                }
            }

#pragma unroll
            for (int mt = 0; mt < 2; mt++) {
#pragma unroll
                for (int nt = 0; nt < 4; nt++) {
                    float* r0p = red + (size_t)(w * 32 + mt * 16 + m) * 52 + nt * 8 + n0r;
                    *(float2*)r0p = make_float2(acc[mt][nt][0], acc[mt][nt][1]);
                    *(float2*)(r0p + 8 * 52) = make_float2(acc[mt][nt][2], acc[mt][nt][3]);
                }
#pragma unroll
                for (int nt = 0; nt < 2; nt++) {
                    float* r0p = red + (size_t)(w * 32 + mt * 16 + m) * 52 + 32 + nt * 8 + n0r;
                    *(float2*)r0p = make_float2(acc[mt][4 + nt][0], acc[mt][4 + nt][1]);
                    *(float2*)(r0p + 8 * 52) = make_float2(acc[mt][4 + nt][2], acc[mt][4 + nt][3]);
                }
            }
            __syncthreads();

            float hn2[2];
#pragma unroll
            for (int j = 0; j < 2; j++) {
                int u_loc = u0 + j;
                float zv = 0.f, rv = 0.f, pvv = 0.f, qv = 0.f;
#pragma unroll
                for (int ww = 0; ww < 8; ww++) {
                    const float* rr = red + (size_t)(ww * 32 + b_loc) * 52;
                    zv += rr[u_loc];
                    rv += rr[16 + u_loc];
                    if (ww < 4) pvv += rr[32 + u_loc];
                    else        qv  += rr[32 + u_loc];
                }
                float z  = fsig(zv + cz[j]);
                float r  = fsig(rv + cr[j]);
                float hh = ftanh(pvv + bih[j] + r * (qv + bhh2[j]));
                float hn = z * hown[j] + (1.0f - z) * hh;
                hown[j] = hn;
                hn2[j] = hn;
                out1[(size_t)b_glob * T_ * U_ + (size_t)(s - 1) * U_ + u_base + u_loc] = hn;
                if (s == T_) hl1[(size_t)b_glob * U_ + u_base + u_loc] = hn;
            }
            if (s <= T_ - 1) {
                unsigned pv = (unsigned)__half_as_ushort(__float2half(hn2[0])) |
                              ((unsigned)__half_as_ushort(__float2half(hn2[1])) << 16);
                STG_U32(&g_hx1f[(s - 1) & 1][fwoff], pv);
            }
            __syncthreads();
            if (tid == 0) bar_arrive(c1);
            ph = (ph == 2) ? 0 : ph + 1;
        }
    }
}

// ---------------- launcher ----------------
extern "C" void kernel_launch(void* const* d_in, const int* in_sizes, int n_in,
                              void* d_out, int out_size) {
    const float* x  = (const float*)d_in[0];
    const float* W0 = (const float*)d_in[1];
    const float* R0 = (const float*)d_in[2];
    const float* b0 = (const float*)d_in[3];
    const float* W1 = (const float*)d_in[4];
    const float* R1 = (const float*)d_in[5];
    const float* b1 = (const float*)d_in[6];

    float* out  = (float*)d_out;
    float* out1 = out;                               // [64,1024,512]
    float* h0   = out + (size_t)B_ * T_ * U_;        // [64,512]
    float* h1   = h0 + (size_t)B_ * U_;              // [64,512]

    cudaFuncSetAttribute(wave_rec, cudaFuncAttributeMaxDynamicSharedMemorySize,
                         SMEM_WAVE);
    cudaFuncSetAttribute(gemm_mma, cudaFuncAttributeMaxDynamicSharedMemorySize,
                         SMEM_GEMM);

    prep_weights<<<NC_ * U_ / 256, 256>>>(W0, W1, R0, R1);       // 0
    split_x<<<4096, 256>>>(x);                                   // 1
    dim3 gc0(12, 64);
    gemm_mma<<<gc0, 256, SMEM_GEMM>>>(b0);                       // 2: chunk 0 only
    wave_rec<<<148, 256, SMEM_WAVE>>>(b0, b1, out1, h0, h1);     // 3 -> ncu
}